// round 6
// baseline (speedup 1.0000x reference)
#include <cuda_runtime.h>

// ---------------------------------------------------------------------------
// ESABotRGCN 4-layer pipeline. fp32 throughout; GEMMs use fma.rn.f32x2.
// ---------------------------------------------------------------------------
#define NMAX 100000
#define EMAX 600000

typedef unsigned long long ull;

// ------------------------- scratch (device globals) ------------------------
__device__ float g_bufA[(size_t)NMAX * 128];
__device__ float g_bufB[(size_t)NMAX * 128];
__device__ float g_y   [(size_t)NMAX * 384];   // [root | rel0 | rel1]

__device__ int g_c0[NMAX];
__device__ int g_c1[NMAX];
__device__ int g_rp[NMAX + 1];
__device__ int g_cur[NMAX];
__device__ int g_ep[EMAX];                     // (src<<1)|rel
__device__ int g_bsum[128];
__device__ int g_boff[128];

// ------------------------------ f32x2 helpers ------------------------------
__device__ __forceinline__ ull pack2(float f) {
    unsigned u = __float_as_uint(f);
    ull r;
    asm("mov.b64 %0, {%1, %2};" : "=l"(r) : "r"(u), "r"(u));
    return r;
}
__device__ __forceinline__ void fma2(ull& d, ull a, ull b) {
    asm("fma.rn.f32x2 %0, %1, %2, %0;" : "+l"(d) : "l"(a), "l"(b));
}
__device__ __forceinline__ float2 unpack2(ull v) {
    unsigned lo, hi;
    asm("mov.b64 {%0, %1}, %2;" : "=r"(lo), "=r"(hi) : "l"(v));
    return make_float2(__uint_as_float(lo), __uint_as_float(hi));
}
__device__ __forceinline__ float lrelu(float v) { return fmaxf(v, 0.01f * v); }

// ------------------------------- CSR build ---------------------------------
__global__ void k_zero(int n) {
    int i = blockIdx.x * blockDim.x + threadIdx.x;
    if (i < n) { g_c0[i] = 0; g_c1[i] = 0; }
}

__global__ void k_hist(const int* __restrict__ ei, const int* __restrict__ et,
                       int nE) {
    int i = blockIdx.x * blockDim.x + threadIdx.x;
    if (i >= nE) return;
    int d = ei[nE + i];
    if (et[i]) atomicAdd(&g_c1[d], 1);
    else       atomicAdd(&g_c0[d], 1);
}

__global__ void k_scan1(int n) {  // 1024 thr/block: block-local exclusive scan
    int tid = threadIdx.x;
    int i = blockIdx.x * 1024 + tid;
    int v = (i < n) ? (g_c0[i] + g_c1[i]) : 0;
    int x = v;
    int lane = tid & 31, w = tid >> 5;
#pragma unroll
    for (int d = 1; d < 32; d <<= 1) {
        int t = __shfl_up_sync(0xffffffffu, x, d);
        if (lane >= d) x += t;
    }
    __shared__ int wt[32];
    if (lane == 31) wt[w] = x;
    __syncthreads();
    if (w == 0) {
        int y = wt[lane];
#pragma unroll
        for (int d = 1; d < 32; d <<= 1) {
            int t = __shfl_up_sync(0xffffffffu, y, d);
            if (lane >= d) y += t;
        }
        wt[lane] = y;
    }
    __syncthreads();
    int off = (w > 0) ? wt[w - 1] : 0;
    int inc = x + off;
    if (i < n) g_rp[i] = inc - v;
    if (tid == 1023) g_bsum[blockIdx.x] = inc;
}

__global__ void k_scan2(int nb, int n, int nE) {  // single block, 128 threads
    int t = threadIdx.x;
    int lane = t & 31, w = t >> 5;
    int v = (t < nb) ? g_bsum[t] : 0;
    int x = v;
#pragma unroll
    for (int d = 1; d < 32; d <<= 1) {
        int s = __shfl_up_sync(0xffffffffu, x, d);
        if (lane >= d) x += s;
    }
    __shared__ int wt[4];
    if (lane == 31) wt[w] = x;
    __syncthreads();
    int off = 0;
    for (int k = 0; k < w; k++) off += wt[k];
    g_boff[t] = x + off - v;
    if (t == 0) g_rp[n] = nE;
}

__global__ void k_scan3(int n) {
    int i = blockIdx.x * blockDim.x + threadIdx.x;
    if (i >= n) return;
    int v = g_rp[i] + g_boff[i >> 10];
    g_rp[i] = v;
    g_cur[i] = v;
}

__global__ void k_fill(const int* __restrict__ ei, const int* __restrict__ et,
                       int nE) {
    int i = blockIdx.x * blockDim.x + threadIdx.x;
    if (i >= nE) return;
    int d = ei[nE + i];
    int pos = atomicAdd(&g_cur[d], 1);
    g_ep[pos] = (ei[i] << 1) | (et[i] ? 1 : 0);
}

// --------------------------- small embeddings ------------------------------
// cols 64..127 of bufA: num(12) | cat(40) | new(12), all lrelu'd
__global__ void k_small(const float* __restrict__ num,
                        const float* __restrict__ cat,
                        const float* __restrict__ nf,
                        const float* __restrict__ Wn, const float* __restrict__ bn,
                        const float* __restrict__ Wc, const float* __restrict__ bc,
                        const float* __restrict__ Ww, const float* __restrict__ bw,
                        float* __restrict__ xcat, int n) {
    int g = blockIdx.x * blockDim.x + threadIdx.x;
    if (g >= n * 64) return;
    int i = g >> 6, j = g & 63;
    float v;
    if (j < 12) {
        float s = bn[j];
#pragma unroll
        for (int k = 0; k < 7; k++)
            s = fmaf(num[(size_t)i * 7 + k], Wn[k * 12 + j], s);
        v = s;
    } else if (j < 52) {
        int c = j - 12;
        float s = bc[c];
#pragma unroll
        for (int k = 0; k < 11; k++)
            s = fmaf(cat[(size_t)i * 11 + k], Wc[k * 40 + c], s);
        v = s;
    } else {
        int c = j - 52;
        v = fmaf(nf[i], Ww[c], bw[c]);
    }
    xcat[(size_t)i * 128 + 64 + j] = lrelu(v);
}

// ------------------------------- GEMM (f32x2) ------------------------------
// C[:, coff + cb .. ] = act(A[M,KTOT] @ W[KTOT,NC] + bias), row stride ldc.
template <int KTOT, int BK, int BM, int BN, int TM, int TN, int NT, bool ACT>
__global__ void __launch_bounds__(NT)
gemm_f2(const float* __restrict__ A, const float* __restrict__ W,
        const float* __restrict__ bias, float* __restrict__ C,
        int M, int NC, int ldc, int coff) {
    constexpr int RG = BM / TM;
    constexpr int CG = BN / TN;
    static_assert(RG * CG == NT, "tiling");
    static_assert((TM & 1) == 0 && (BK & 3) == 0, "shape");
    constexpr int BMP = BM + 2;

    __shared__ float sA[BK][BMP];   // transposed: [k][m]
    __shared__ float sW[BK][BN];

    int tid = threadIdx.x;
    int tx = tid % CG;
    int ty = tid / CG;
    int m0 = blockIdx.x * BM;
    int cb = blockIdx.y * BN;
    int rb = ty * TM;

    ull acc[TM / 2][TN];
#pragma unroll
    for (int p = 0; p < TM / 2; p++)
#pragma unroll
        for (int j = 0; j < TN; j++) acc[p][j] = 0ull;

    for (int k0 = 0; k0 < KTOT; k0 += BK) {
        // A tile: vectorized float4, stored transposed
        for (int idx = tid; idx < BM * (BK / 4); idx += NT) {
            int kq = idx % (BK / 4);
            int m  = idx / (BK / 4);
            float4 v = make_float4(0.f, 0.f, 0.f, 0.f);
            if (m0 + m < M)
                v = *(const float4*)&A[(size_t)(m0 + m) * KTOT + k0 + kq * 4];
            sA[kq * 4 + 0][m] = v.x;
            sA[kq * 4 + 1][m] = v.y;
            sA[kq * 4 + 2][m] = v.z;
            sA[kq * 4 + 3][m] = v.w;
        }
        // W tile: coalesced over columns, zero-pad cols >= NC
        for (int idx = tid; idx < BK * BN; idx += NT) {
            int c = idx % BN, k = idx / BN;
            int gc = cb + c;
            sW[k][c] = (gc < NC) ? W[(size_t)(k0 + k) * NC + gc] : 0.f;
        }
        __syncthreads();

#pragma unroll
        for (int kk = 0; kk < BK; kk++) {
            ull wd[TN];
            if (TN == 8) {
                float4 w0 = *(const float4*)&sW[kk][tx * 8];
                float4 w1 = *(const float4*)&sW[kk][tx * 8 + 4];
                wd[0] = pack2(w0.x); wd[1] = pack2(w0.y);
                wd[2] = pack2(w0.z); wd[3] = pack2(w0.w);
                wd[4] = pack2(w1.x); wd[5] = pack2(w1.y);
                wd[6] = pack2(w1.z); wd[7] = pack2(w1.w);
            } else {  // TN == 4
                float4 w0 = *(const float4*)&sW[kk][tx * 4];
                wd[0] = pack2(w0.x); wd[1] = pack2(w0.y);
                wd[2] = pack2(w0.z); wd[3] = pack2(w0.w);
            }
            ull ap[TM / 2];
#pragma unroll
            for (int p = 0; p < TM / 2; p++)
                ap[p] = *(const ull*)&sA[kk][rb + 2 * p];
#pragma unroll
            for (int p = 0; p < TM / 2; p++)
#pragma unroll
                for (int j = 0; j < TN; j++) fma2(acc[p][j], ap[p], wd[j]);
        }
        __syncthreads();
    }

    float bj[TN];
#pragma unroll
    for (int j = 0; j < TN; j++) {
        int gc = cb + tx * TN + j;
        bj[j] = (bias != nullptr && gc < NC) ? bias[gc] : 0.f;
    }
#pragma unroll
    for (int p = 0; p < TM / 2; p++) {
        int r0 = m0 + rb + 2 * p;
#pragma unroll
        for (int j = 0; j < TN; j++) {
            int gc = cb + tx * TN + j;
            if (gc >= NC) continue;
            float2 v = unpack2(acc[p][j]);
            if (r0 < M) {
                float o = v.x + bj[j];
                if (ACT) o = lrelu(o);
                C[(size_t)r0 * ldc + coff + gc] = o;
            }
            if (r0 + 1 < M) {
                float o = v.y + bj[j];
                if (ACT) o = lrelu(o);
                C[(size_t)(r0 + 1) * ldc + coff + gc] = o;
            }
        }
    }
}

// --------------------------- RGCN mean aggregation -------------------------
// out[i] = y_root[i] + sum_r (sum over rel-r in-edges of y_r[src]) / max(c_r,1)
__global__ void k_agg(const float* __restrict__ y, float* __restrict__ out,
                      int n) {
    int g = blockIdx.x * blockDim.x + threadIdx.x;
    int gw = g >> 5;
    if (gw >= n) return;
    int lane = g & 31;
    int beg = g_rp[gw], end = g_rp[gw + 1];
    float4 a0 = make_float4(0.f, 0.f, 0.f, 0.f);
    float4 a1 = make_float4(0.f, 0.f, 0.f, 0.f);
    for (int e = beg; e < end; e++) {
        int p = g_ep[e];
        int r = p & 1;
        const float4* v4 =
            (const float4*)(y + (size_t)(p >> 1) * 384 + 128 + (r << 7));
        float4 v = v4[lane];
        if (r) { a1.x += v.x; a1.y += v.y; a1.z += v.z; a1.w += v.w; }
        else   { a0.x += v.x; a0.y += v.y; a0.z += v.z; a0.w += v.w; }
    }
    int c0 = g_c0[gw]; if (c0 < 1) c0 = 1;
    int c1 = g_c1[gw]; if (c1 < 1) c1 = 1;
    float r0 = 1.f / (float)c0;
    float r1 = 1.f / (float)c1;
    float4 o = ((const float4*)(y + (size_t)gw * 384))[lane];
    o.x += a0.x * r0 + a1.x * r1;
    o.y += a0.y * r0 + a1.y * r1;
    o.z += a0.z * r0 + a1.z * r1;
    o.w += a0.w * r0 + a1.w * r1;
    ((float4*)(out + (size_t)gw * 128))[lane] = o;
}

// ------------------------------ final linear -------------------------------
__global__ void k_final(const float* __restrict__ h, const float* __restrict__ W2,
                        const float* __restrict__ b2, float* __restrict__ out,
                        int n) {
    int g = blockIdx.x * blockDim.x + threadIdx.x;
    int gw = g >> 5;
    if (gw >= n) return;
    int lane = g & 31;
    const float* hr = h + (size_t)gw * 128;
    float a0 = 0.f, a1 = 0.f;
#pragma unroll
    for (int t = 0; t < 4; t++) {
        int k = lane + 32 * t;
        float hv = hr[k];
        float2 w = *(const float2*)&W2[k * 2];
        a0 = fmaf(hv, w.x, a0);
        a1 = fmaf(hv, w.y, a1);
    }
#pragma unroll
    for (int o = 16; o > 0; o >>= 1) {
        a0 += __shfl_xor_sync(0xffffffffu, a0, o);
        a1 += __shfl_xor_sync(0xffffffffu, a1, o);
    }
    if (lane == 0) {
        out[(size_t)gw * 2]     = a0 + b2[0];
        out[(size_t)gw * 2 + 1] = a1 + b2[1];
    }
}

// --------------------------------- launch ----------------------------------
extern "C" void kernel_launch(void* const* d_in, const int* in_sizes, int n_in,
                              void* d_out, int out_size) {
    const float* des    = (const float*)d_in[0];
    const float* tweet  = (const float*)d_in[1];
    const float* num    = (const float*)d_in[2];
    const float* cat    = (const float*)d_in[3];
    const float* nf     = (const float*)d_in[4];
    const int*   ei     = (const int*)  d_in[5];
    const int*   et     = (const int*)  d_in[6];
    const float* W_des  = (const float*)d_in[7];
    const float* b_des  = (const float*)d_in[8];
    const float* W_tw   = (const float*)d_in[9];
    const float* b_tw   = (const float*)d_in[10];
    const float* W_num  = (const float*)d_in[11];
    const float* b_num  = (const float*)d_in[12];
    const float* W_cat  = (const float*)d_in[13];
    const float* b_cat  = (const float*)d_in[14];
    const float* W_new  = (const float*)d_in[15];
    const float* b_new  = (const float*)d_in[16];
    const float* W_in   = (const float*)d_in[17];
    const float* b_in   = (const float*)d_in[18];
    const float* W_root = (const float*)d_in[19];
    const float* W_rel  = (const float*)d_in[20];
    const float* b_rg   = (const float*)d_in[21];
    const float* W_o1   = (const float*)d_in[22];
    const float* b_o1   = (const float*)d_in[23];
    const float* W_o2   = (const float*)d_in[24];
    const float* b_o2   = (const float*)d_in[25];

    int nN = in_sizes[0] / 768;
    int nE = in_sizes[6];
    if (nN > NMAX) nN = NMAX;
    if (nE > EMAX) nE = EMAX;

    float *bufA, *bufB, *bufY;
    cudaGetSymbolAddress((void**)&bufA, g_bufA);
    cudaGetSymbolAddress((void**)&bufB, g_bufB);
    cudaGetSymbolAddress((void**)&bufY, g_y);

    int gm     = (nN + 127) / 128;
    int gN256  = (nN + 255) / 256;
    int gE256  = (nE + 255) / 256;
    int gScan  = (nN + 1023) / 1024;
    int gWarpN = (nN * 32 + 255) / 256;

    // CSR over dst (feature-independent)
    k_zero<<<gN256, 256>>>(nN);
    k_hist<<<gE256, 256>>>(ei, et, nE);
    k_scan1<<<gScan, 1024>>>(nN);
    k_scan2<<<1, 128>>>(gScan, nN, nE);
    k_scan3<<<gN256, 256>>>(nN);
    k_fill<<<gE256, 256>>>(ei, et, nE);

    // Embeddings -> bufA [N,128]
    gemm_f2<768, 16, 128, 32, 8, 4, 128, true>
        <<<gm, 128>>>(des, W_des, b_des, bufA, nN, 28, 128, 0);
    gemm_f2<768, 16, 128, 40, 8, 4, 160, true>
        <<<gm, 160>>>(tweet, W_tw, b_tw, bufA, nN, 36, 128, 28);
    k_small<<<(nN * 64 + 255) / 256, 256>>>(num, cat, nf, W_num, b_num,
                                            W_cat, b_cat, W_new, b_new,
                                            bufA, nN);

    // W_in: bufA -> bufB (lrelu)
    gemm_f2<128, 16, 128, 128, 16, 8, 128, true>
        <<<gm, 128>>>(bufA, W_in, b_in, bufB, nN, 128, 128, 0);

    // 4 RGCN layers, ping-pong bufB <-> bufA through bufY
    float* x  = bufB;
    float* xn = bufA;
    for (int i = 0; i < 4; i++) {
        const float* Wr  = W_root + (size_t)i * 128 * 128;
        const float* W0  = W_rel  + (size_t)(i * 2 + 0) * 128 * 128;
        const float* W1  = W_rel  + (size_t)(i * 2 + 1) * 128 * 128;
        const float* br  = b_rg   + (size_t)i * 128;
        gemm_f2<128, 16, 128, 128, 16, 8, 128, false>
            <<<gm, 128>>>(x, Wr, br, bufY, nN, 128, 384, 0);
        gemm_f2<128, 16, 128, 128, 16, 8, 128, false>
            <<<gm, 128>>>(x, W0, nullptr, bufY, nN, 128, 384, 128);
        gemm_f2<128, 16, 128, 128, 16, 8, 128, false>
            <<<gm, 128>>>(x, W1, nullptr, bufY, nN, 128, 384, 256);
        k_agg<<<gWarpN, 256>>>(bufY, xn, nN);
        float* t = x; x = xn; xn = t;
    }
    // after 4 swaps: x == bufB

    // W_o1: x -> bufA (lrelu)
    gemm_f2<128, 16, 128, 128, 16, 8, 128, true>
        <<<gm, 128>>>(x, W_o1, b_o1, bufA, nN, 128, 128, 0);

    // Final [N,2]
    k_final<<<gWarpN, 256>>>(bufA, W_o2, b_o2, (float*)d_out, nN);
}

// round 9
// speedup vs baseline: 1.7770x; 1.7770x over previous
#include <cuda_runtime.h>
#include <cuda_bf16.h>
#include <cstdint>

// ---------------------------------------------------------------------------
// ESABotRGCN 4-layer pipeline.
//  - 128x128 GEMMs: mma.sync m16n8k16 bf16 (hi/lo split, 3 products, fp32 acc)
//  - 768-K embedding GEMMs: fp32 fma.rn.f32x2 path.
//  - Graph aggregation: CSR over dst + warp-per-node gather, folded weights.
// ---------------------------------------------------------------------------
#define NMAX 100000
#define EMAX 600000

typedef unsigned long long ull;

// ------------------------- scratch (device globals) ------------------------
__device__ float g_bufA[(size_t)NMAX * 128];
__device__ float g_bufB[(size_t)NMAX * 128];
__device__ float g_y   [(size_t)NMAX * 384];   // [root | rel0 | rel1]

__device__ __nv_bfloat16 g_Whi[14 * 128 * 128]; // [mat][n][k]  (W^T, split hi)
__device__ __nv_bfloat16 g_Wlo[14 * 128 * 128]; // [mat][n][k]  (W^T, split lo)

__device__ int g_c0[NMAX];
__device__ int g_c1[NMAX];
__device__ int g_rp[NMAX + 1];
__device__ int g_cur[NMAX];
__device__ int g_ep[EMAX];                     // (src<<1)|rel
__device__ int g_bsum[128];
__device__ int g_boff[128];

// ------------------------------ small helpers ------------------------------
__device__ __forceinline__ float lrelu(float v) { return fmaxf(v, 0.01f * v); }

// f32x2 helpers (embedding GEMMs)
__device__ __forceinline__ ull pack2(float f) {
    unsigned u = __float_as_uint(f);
    ull r;
    asm("mov.b64 %0, {%1, %2};" : "=l"(r) : "r"(u), "r"(u));
    return r;
}
__device__ __forceinline__ void fma2(ull& d, ull a, ull b) {
    asm("fma.rn.f32x2 %0, %1, %2, %0;" : "+l"(d) : "l"(a), "l"(b));
}
__device__ __forceinline__ float2 unpack2(ull v) {
    unsigned lo, hi;
    asm("mov.b64 {%0, %1}, %2;" : "=r"(lo), "=r"(hi) : "l"(v));
    return make_float2(__uint_as_float(lo), __uint_as_float(hi));
}

// ------------------------------- weight prep -------------------------------
// g_Whi/g_Wlo[m][n][k] = split(bf16) of W_m[k][n]   (B col-major for mma)
__global__ void k_wprep(const float* __restrict__ Win,
                        const float* __restrict__ Wroot,
                        const float* __restrict__ Wrel,
                        const float* __restrict__ Wo1) {
    int idx = blockIdx.x * blockDim.x + threadIdx.x;
    if (idx >= 14 * 16384) return;
    int m = idx >> 14;
    int r = idx & 16383;
    int n = r >> 7, k = r & 127;
    const float* src;
    if (m == 0) src = Win;
    else if (m == 13) src = Wo1;
    else {
        int l = (m - 1) / 3, j = (m - 1) % 3;
        src = (j == 0) ? (Wroot + (size_t)l * 16384)
                       : (Wrel + (size_t)(l * 2 + (j - 1)) * 16384);
    }
    float v = src[k * 128 + n];
    __nv_bfloat16 h = __float2bfloat16(v);
    g_Whi[idx] = h;
    g_Wlo[idx] = __float2bfloat16(v - __bfloat162float(h));
}

// ----------------------- HMMA GEMM (bf16 split x3) -------------------------
// C[:, bIdx.y*128 ..] = act(A[M,128] @ W_mat + bias), row stride ldc.
// smem: bias(512B) | buf0(A hi, then A lo) | buf1(B hi) | buf2(B lo)
// row stride 136 bf16 = 272B (bank-conflict-free fragment loads).
#define MMS_BIAS 0
#define MMS_A    512
#define MMS_B1   35328
#define MMS_B2   70144
#define MMS_TOTAL 104960

__device__ __forceinline__ void mma16816(float* c, const uint32_t* a,
                                         uint32_t b0, uint32_t b1) {
    asm volatile(
        "mma.sync.aligned.m16n8k16.row.col.f32.bf16.bf16.f32 "
        "{%0,%1,%2,%3}, {%4,%5,%6,%7}, {%8,%9}, {%0,%1,%2,%3};"
        : "+f"(c[0]), "+f"(c[1]), "+f"(c[2]), "+f"(c[3])
        : "r"(a[0]), "r"(a[1]), "r"(a[2]), "r"(a[3]), "r"(b0), "r"(b1));
}

// accumulate: acc += (smem A tile) @ (smem B tile)^T over K=128
__device__ __forceinline__ void mm_prod(const char* pa, const char* pb,
                                        int wm0, int wn0, int lane,
                                        float acc[2][8][4]) {
#pragma unroll
    for (int ks = 0; ks < 8; ks++) {
        uint32_t a[2][4];
#pragma unroll
        for (int mt = 0; mt < 2; mt++) {
            const char* ap = pa + (wm0 + mt * 16 + (lane >> 2)) * 272 +
                             (lane & 3) * 4 + ks * 32;
            a[mt][0] = *(const uint32_t*)ap;
            a[mt][1] = *(const uint32_t*)(ap + 8 * 272);
            a[mt][2] = *(const uint32_t*)(ap + 16);
            a[mt][3] = *(const uint32_t*)(ap + 8 * 272 + 16);
        }
#pragma unroll
        for (int nt = 0; nt < 8; nt++) {
            const char* bp = pb + (wn0 + nt * 8 + (lane >> 2)) * 272 +
                             (lane & 3) * 4 + ks * 32;
            uint32_t b0 = *(const uint32_t*)bp;
            uint32_t b1 = *(const uint32_t*)(bp + 16);
            mma16816(acc[0][nt], a[0], b0, b1);
            mma16816(acc[1][nt], a[1], b0, b1);
        }
    }
}

template <bool ACT>
__global__ void __launch_bounds__(256, 2)
mm_hmma(const float* __restrict__ A, int matBase,
        const float* __restrict__ bias, float* __restrict__ C,
        int M, int ldc) {
    extern __shared__ char sm[];
    float* sbias = (float*)(sm + MMS_BIAS);
    char* sA  = sm + MMS_A;
    char* sB1 = sm + MMS_B1;
    char* sB2 = sm + MMS_B2;

    int tid = threadIdx.x;
    int lane = tid & 31, wid = tid >> 5;
    int m0 = blockIdx.x * 128;
    int mat = matBase + blockIdx.y;

    if (tid < 128)
        sbias[tid] = (bias != nullptr && blockIdx.y == 0) ? bias[tid] : 0.f;

    // A hi tile
    for (int t = tid; t < 2048; t += 256) {
        int row = t >> 4, cq = t & 15;
        int gr = m0 + row;
        float x[8];
#pragma unroll
        for (int i = 0; i < 8; i++) x[i] = 0.f;
        if (gr < M) {
            float4 a0 = *(const float4*)&A[(size_t)gr * 128 + cq * 8];
            float4 a1 = *(const float4*)&A[(size_t)gr * 128 + cq * 8 + 4];
            x[0] = a0.x; x[1] = a0.y; x[2] = a0.z; x[3] = a0.w;
            x[4] = a1.x; x[5] = a1.y; x[6] = a1.z; x[7] = a1.w;
        }
        __nv_bfloat16 h[8];
#pragma unroll
        for (int i = 0; i < 8; i++) h[i] = __float2bfloat16(x[i]);
        *(uint4*)(sA + row * 272 + cq * 16) = *(const uint4*)h;
    }
    // B hi/lo tiles
    {
        const uint4* srcH = (const uint4*)(g_Whi + (size_t)mat * 16384);
        const uint4* srcL = (const uint4*)(g_Wlo + (size_t)mat * 16384);
        for (int t = tid; t < 2048; t += 256) {
            int n = t >> 4, kq = t & 15;
            *(uint4*)(sB1 + n * 272 + kq * 16) = srcH[t];
            *(uint4*)(sB2 + n * 272 + kq * 16) = srcL[t];
        }
    }
    __syncthreads();

    int wm0 = (wid >> 1) * 32;
    int wn0 = (wid & 1) * 64;

    float acc[2][8][4];
#pragma unroll
    for (int mt = 0; mt < 2; mt++)
#pragma unroll
        for (int nt = 0; nt < 8; nt++)
#pragma unroll
            for (int q = 0; q < 4; q++) acc[mt][nt][q] = 0.f;

    mm_prod(sA, sB1, wm0, wn0, lane, acc);   // Ah * Bh
    mm_prod(sA, sB2, wm0, wn0, lane, acc);   // Ah * Bl
    __syncthreads();

    // overwrite sA with A lo
    for (int t = tid; t < 2048; t += 256) {
        int row = t >> 4, cq = t & 15;
        int gr = m0 + row;
        float x[8];
#pragma unroll
        for (int i = 0; i < 8; i++) x[i] = 0.f;
        if (gr < M) {
            float4 a0 = *(const float4*)&A[(size_t)gr * 128 + cq * 8];
            float4 a1 = *(const float4*)&A[(size_t)gr * 128 + cq * 8 + 4];
            x[0] = a0.x; x[1] = a0.y; x[2] = a0.z; x[3] = a0.w;
            x[4] = a1.x; x[5] = a1.y; x[6] = a1.z; x[7] = a1.w;
        }
        __nv_bfloat16 l[8];
#pragma unroll
        for (int i = 0; i < 8; i++) {
            __nv_bfloat16 h = __float2bfloat16(x[i]);
            l[i] = __float2bfloat16(x[i] - __bfloat162float(h));
        }
        *(uint4*)(sA + row * 272 + cq * 16) = *(const uint4*)l;
    }
    __syncthreads();

    mm_prod(sA, sB1, wm0, wn0, lane, acc);   // Al * Bh

    // epilogue
    float2 b2[8];
#pragma unroll
    for (int nt = 0; nt < 8; nt++) {
        int c = wn0 + nt * 8 + (lane & 3) * 2;
        b2[nt] = make_float2(sbias[c], sbias[c + 1]);
    }
    int coff = blockIdx.y * 128;
#pragma unroll
    for (int mt = 0; mt < 2; mt++) {
        int r0 = m0 + wm0 + mt * 16 + (lane >> 2);
#pragma unroll
        for (int nt = 0; nt < 8; nt++) {
            int c = coff + wn0 + nt * 8 + (lane & 3) * 2;
            if (r0 < M) {
                float2 o = make_float2(acc[mt][nt][0] + b2[nt].x,
                                       acc[mt][nt][1] + b2[nt].y);
                if (ACT) { o.x = lrelu(o.x); o.y = lrelu(o.y); }
                *(float2*)&C[(size_t)r0 * ldc + c] = o;
            }
            if (r0 + 8 < M) {
                float2 o = make_float2(acc[mt][nt][2] + b2[nt].x,
                                       acc[mt][nt][3] + b2[nt].y);
                if (ACT) { o.x = lrelu(o.x); o.y = lrelu(o.y); }
                *(float2*)&C[(size_t)(r0 + 8) * ldc + c] = o;
            }
        }
    }
}

// ------------------------------- CSR build ---------------------------------
__global__ void k_zero(int n) {
    int i = blockIdx.x * blockDim.x + threadIdx.x;
    if (i < n) { g_c0[i] = 0; g_c1[i] = 0; }
}

__global__ void k_hist(const int* __restrict__ ei, const int* __restrict__ et,
                       int nE) {
    int i = blockIdx.x * blockDim.x + threadIdx.x;
    if (i >= nE) return;
    int d = ei[nE + i];
    if (et[i]) atomicAdd(&g_c1[d], 1);
    else       atomicAdd(&g_c0[d], 1);
}

__global__ void k_scan1(int n) {
    int tid = threadIdx.x;
    int i = blockIdx.x * 1024 + tid;
    int v = (i < n) ? (g_c0[i] + g_c1[i]) : 0;
    int x = v;
    int lane = tid & 31, w = tid >> 5;
#pragma unroll
    for (int d = 1; d < 32; d <<= 1) {
        int t = __shfl_up_sync(0xffffffffu, x, d);
        if (lane >= d) x += t;
    }
    __shared__ int wt[32];
    if (lane == 31) wt[w] = x;
    __syncthreads();
    if (w == 0) {
        int y = wt[lane];
#pragma unroll
        for (int d = 1; d < 32; d <<= 1) {
            int t = __shfl_up_sync(0xffffffffu, y, d);
            if (lane >= d) y += t;
        }
        wt[lane] = y;
    }
    __syncthreads();
    int off = (w > 0) ? wt[w - 1] : 0;
    int inc = x + off;
    if (i < n) g_rp[i] = inc - v;
    if (tid == 1023) g_bsum[blockIdx.x] = inc;
}

__global__ void k_scan2(int nb, int n, int nE) {
    int t = threadIdx.x;
    int lane = t & 31, w = t >> 5;
    int v = (t < nb) ? g_bsum[t] : 0;
    int x = v;
#pragma unroll
    for (int d = 1; d < 32; d <<= 1) {
        int s = __shfl_up_sync(0xffffffffu, x, d);
        if (lane >= d) x += s;
    }
    __shared__ int wt[4];
    if (lane == 31) wt[w] = x;
    __syncthreads();
    int off = 0;
    for (int k = 0; k < w; k++) off += wt[k];
    g_boff[t] = x + off - v;
    if (t == 0) g_rp[n] = nE;
}

__global__ void k_scan3(int n) {
    int i = blockIdx.x * blockDim.x + threadIdx.x;
    if (i >= n) return;
    int v = g_rp[i] + g_boff[i >> 10];
    g_rp[i] = v;
    g_cur[i] = v;
}

__global__ void k_fill(const int* __restrict__ ei, const int* __restrict__ et,
                       int nE) {
    int i = blockIdx.x * blockDim.x + threadIdx.x;
    if (i >= nE) return;
    int d = ei[nE + i];
    int pos = atomicAdd(&g_cur[d], 1);
    g_ep[pos] = (ei[i] << 1) | (et[i] ? 1 : 0);
}

// --------------------------- small embeddings ------------------------------
__global__ void k_small(const float* __restrict__ num,
                        const float* __restrict__ cat,
                        const float* __restrict__ nf,
                        const float* __restrict__ Wn, const float* __restrict__ bn,
                        const float* __restrict__ Wc, const float* __restrict__ bc,
                        const float* __restrict__ Ww, const float* __restrict__ bw,
                        float* __restrict__ xcat, int n) {
    int g = blockIdx.x * blockDim.x + threadIdx.x;
    if (g >= n * 64) return;
    int i = g >> 6, j = g & 63;
    float v;
    if (j < 12) {
        float s = bn[j];
#pragma unroll
        for (int k = 0; k < 7; k++)
            s = fmaf(num[(size_t)i * 7 + k], Wn[k * 12 + j], s);
        v = s;
    } else if (j < 52) {
        int c = j - 12;
        float s = bc[c];
#pragma unroll
        for (int k = 0; k < 11; k++)
            s = fmaf(cat[(size_t)i * 11 + k], Wc[k * 40 + c], s);
        v = s;
    } else {
        int c = j - 52;
        v = fmaf(nf[i], Ww[c], bw[c]);
    }
    xcat[(size_t)i * 128 + 64 + j] = lrelu(v);
}

// -------------------------- f32x2 GEMM (embeddings) ------------------------
template <int KTOT, int BK, int BM, int BN, int TM, int TN, int NT, bool ACT>
__global__ void __launch_bounds__(NT)
gemm_f2(const float* __restrict__ A, const float* __restrict__ W,
        const float* __restrict__ bias, float* __restrict__ C,
        int M, int NC, int ldc, int coff) {
    constexpr int CG = BN / TN;
    constexpr int BMP = BM + 2;
    __shared__ float sA[BK][BMP];
    __shared__ float sW[BK][BN];

    int tid = threadIdx.x;
    int tx = tid % CG;
    int ty = tid / CG;
    int m0 = blockIdx.x * BM;
    int cb = blockIdx.y * BN;
    int rb = ty * TM;

    ull acc[TM / 2][TN];
#pragma unroll
    for (int p = 0; p < TM / 2; p++)
#pragma unroll
        for (int j = 0; j < TN; j++) acc[p][j] = 0ull;

    for (int k0 = 0; k0 < KTOT; k0 += BK) {
        for (int idx = tid; idx < BM * (BK / 4); idx += NT) {
            int kq = idx % (BK / 4);
            int m  = idx / (BK / 4);
            float4 v = make_float4(0.f, 0.f, 0.f, 0.f);
            if (m0 + m < M)
                v = *(const float4*)&A[(size_t)(m0 + m) * KTOT + k0 + kq * 4];
            sA[kq * 4 + 0][m] = v.x;
            sA[kq * 4 + 1][m] = v.y;
            sA[kq * 4 + 2][m] = v.z;
            sA[kq * 4 + 3][m] = v.w;
        }
        for (int idx = tid; idx < BK * BN; idx += NT) {
            int c = idx % BN, k = idx / BN;
            int gc = cb + c;
            sW[k][c] = (gc < NC) ? W[(size_t)(k0 + k) * NC + gc] : 0.f;
        }
        __syncthreads();

#pragma unroll
        for (int kk = 0; kk < BK; kk++) {
            ull wd[TN];
            float4 w0 = *(const float4*)&sW[kk][tx * 4];
            wd[0] = pack2(w0.x); wd[1] = pack2(w0.y);
            wd[2] = pack2(w0.z); wd[3] = pack2(w0.w);
            ull ap[TM / 2];
#pragma unroll
            for (int p = 0; p < TM / 2; p++)
                ap[p] = *(const ull*)&sA[kk][rb + 2 * p];
#pragma unroll
            for (int p = 0; p < TM / 2; p++)
#pragma unroll
                for (int j = 0; j < TN; j++) fma2(acc[p][j], ap[p], wd[j]);
        }
        __syncthreads();
    }

    float bj[TN];
#pragma unroll
    for (int j = 0; j < TN; j++) {
        int gc = cb + tx * TN + j;
        bj[j] = (bias != nullptr && gc < NC) ? bias[gc] : 0.f;
    }
#pragma unroll
    for (int p = 0; p < TM / 2; p++) {
        int r0 = m0 + rb + 2 * p;
#pragma unroll
        for (int j = 0; j < TN; j++) {
            int gc = cb + tx * TN + j;
            if (gc >= NC) continue;
            float2 v = unpack2(acc[p][j]);
            if (r0 < M) {
                float o = v.x + bj[j];
                if (ACT) o = lrelu(o);
                C[(size_t)r0 * ldc + coff + gc] = o;
            }
            if (r0 + 1 < M) {
                float o = v.y + bj[j];
                if (ACT) o = lrelu(o);
                C[(size_t)(r0 + 1) * ldc + coff + gc] = o;
            }
        }
    }
}

// --------------------------- RGCN mean aggregation -------------------------
__global__ void k_agg(const float* __restrict__ y, float* __restrict__ out,
                      int n) {
    int g = blockIdx.x * blockDim.x + threadIdx.x;
    int gw = g >> 5;
    if (gw >= n) return;
    int lane = g & 31;
    int beg = g_rp[gw], end = g_rp[gw + 1];
    int c0 = g_c0[gw]; if (c0 < 1) c0 = 1;
    int c1 = g_c1[gw]; if (c1 < 1) c1 = 1;
    float w0 = 1.f / (float)c0;
    float w1 = 1.f / (float)c1;
    float4 o = ((const float4*)(y + (size_t)gw * 384))[lane];
    for (int e = beg; e < end; e++) {
        int p = g_ep[e];
        int r = p & 1;
        float wgt = r ? w1 : w0;
        const float4* v4 =
            (const float4*)(y + (size_t)(p >> 1) * 384 + 128 + (r << 7));
        float4 v = v4[lane];
        o.x = fmaf(v.x, wgt, o.x);
        o.y = fmaf(v.y, wgt, o.y);
        o.z = fmaf(v.z, wgt, o.z);
        o.w = fmaf(v.w, wgt, o.w);
    }
    ((float4*)(out + (size_t)gw * 128))[lane] = o;
}

// ------------------------------ final linear -------------------------------
__global__ void k_final(const float* __restrict__ h, const float* __restrict__ W2,
                        const float* __restrict__ b2, float* __restrict__ out,
                        int n) {
    int g = blockIdx.x * blockDim.x + threadIdx.x;
    int gw = g >> 5;
    if (gw >= n) return;
    int lane = g & 31;
    const float* hr = h + (size_t)gw * 128;
    float a0 = 0.f, a1 = 0.f;
#pragma unroll
    for (int t = 0; t < 4; t++) {
        int k = lane + 32 * t;
        float hv = hr[k];
        float2 w = *(const float2*)&W2[k * 2];
        a0 = fmaf(hv, w.x, a0);
        a1 = fmaf(hv, w.y, a1);
    }
#pragma unroll
    for (int o = 16; o > 0; o >>= 1) {
        a0 += __shfl_xor_sync(0xffffffffu, a0, o);
        a1 += __shfl_xor_sync(0xffffffffu, a1, o);
    }
    if (lane == 0) {
        out[(size_t)gw * 2]     = a0 + b2[0];
        out[(size_t)gw * 2 + 1] = a1 + b2[1];
    }
}

// --------------------------------- launch ----------------------------------
extern "C" void kernel_launch(void* const* d_in, const int* in_sizes, int n_in,
                              void* d_out, int out_size) {
    const float* des    = (const float*)d_in[0];
    const float* tweet  = (const float*)d_in[1];
    const float* num    = (const float*)d_in[2];
    const float* cat    = (const float*)d_in[3];
    const float* nf     = (const float*)d_in[4];
    const int*   ei     = (const int*)  d_in[5];
    const int*   et     = (const int*)  d_in[6];
    const float* W_des  = (const float*)d_in[7];
    const float* b_des  = (const float*)d_in[8];
    const float* W_tw   = (const float*)d_in[9];
    const float* b_tw   = (const float*)d_in[10];
    const float* W_num  = (const float*)d_in[11];
    const float* b_num  = (const float*)d_in[12];
    const float* W_cat  = (const float*)d_in[13];
    const float* b_cat  = (const float*)d_in[14];
    const float* W_new  = (const float*)d_in[15];
    const float* b_new  = (const float*)d_in[16];
    const float* W_in   = (const float*)d_in[17];
    const float* b_in   = (const float*)d_in[18];
    const float* W_root = (const float*)d_in[19];
    const float* W_rel  = (const float*)d_in[20];
    const float* b_rg   = (const float*)d_in[21];
    const float* W_o1   = (const float*)d_in[22];
    const float* b_o1   = (const float*)d_in[23];
    const float* W_o2   = (const float*)d_in[24];
    const float* b_o2   = (const float*)d_in[25];

    int nN = in_sizes[0] / 768;
    int nE = in_sizes[6];
    if (nN > NMAX) nN = NMAX;
    if (nE > EMAX) nE = EMAX;

    float *bufA, *bufB, *bufY;
    cudaGetSymbolAddress((void**)&bufA, g_bufA);
    cudaGetSymbolAddress((void**)&bufB, g_bufB);
    cudaGetSymbolAddress((void**)&bufY, g_y);

    cudaFuncSetAttribute(mm_hmma<true>,
                         cudaFuncAttributeMaxDynamicSharedMemorySize, MMS_TOTAL);
    cudaFuncSetAttribute(mm_hmma<false>,
                         cudaFuncAttributeMaxDynamicSharedMemorySize, MMS_TOTAL);

    int gm     = (nN + 127) / 128;
    int gN256  = (nN + 255) / 256;
    int gE256  = (nE + 255) / 256;
    int gScan  = (nN + 1023) / 1024;
    int gWarpN = (nN * 32 + 255) / 256;

    // 1: weight prep (split + transpose -> bf16 hi/lo)
    k_wprep<<<(14 * 16384 + 255) / 256, 256>>>(W_in, W_root, W_rel, W_o1);
    // 2: small embeddings
    k_small<<<(nN * 64 + 255) / 256, 256>>>(num, cat, nf, W_num, b_num,
                                            W_cat, b_cat, W_new, b_new,
                                            bufA, nN);
    // 3,4: big embeddings (f32x2)
    gemm_f2<768, 16, 128, 32, 8, 4, 128, true>
        <<<gm, 128>>>(des, W_des, b_des, bufA, nN, 28, 128, 0);
    gemm_f2<768, 16, 128, 40, 8, 4, 160, true>
        <<<gm, 160>>>(tweet, W_tw, b_tw, bufA, nN, 36, 128, 28);

    // 5: W_in (HMMA): bufA -> bufB, lrelu
    mm_hmma<true><<<dim3(gm, 1), 256, MMS_TOTAL>>>(bufA, 0, b_in, bufB, nN, 128);

    // 6-11: CSR over dst
    k_zero<<<gN256, 256>>>(nN);
    k_hist<<<gE256, 256>>>(ei, et, nE);
    k_scan1<<<gScan, 1024>>>(nN);
    k_scan2<<<1, 128>>>(gScan, nN, nE);
    k_scan3<<<gN256, 256>>>(nN);
    k_fill<<<gE256, 256>>>(ei, et, nE);

    // 4 RGCN layers: x -> y[root|rel0|rel1] (HMMA, grid.y=3) -> aggregate
    float* x  = bufB;
    float* xn = bufA;
    for (int l = 0; l < 4; l++) {
        mm_hmma<false><<<dim3(gm, 3), 256, MMS_TOTAL>>>(
            x, 1 + 3 * l, b_rg + (size_t)l * 128, bufY, nN, 384);
        k_agg<<<gWarpN, 256>>>(bufY, xn, nN);
        float* t = x; x = xn; xn = t;
    }
    // after 4 swaps: x == bufB

    // W_o1 (HMMA): x -> bufA, lrelu
    mm_hmma<true><<<dim3(gm, 1), 256, MMS_TOTAL>>>(x, 13, b_o1, bufA, nN, 128);

    // final [N,2]
    k_final<<<gWarpN, 256>>>(bufA, W_o2, b_o2, (float*)d_out, nN);
}

// round 11
// speedup vs baseline: 2.2483x; 1.2652x over previous
#include <cuda_runtime.h>
#include <cuda_bf16.h>
#include <cstdint>

// ---------------------------------------------------------------------------
// ESABotRGCN 4-layer pipeline.
//  - All large GEMMs: mma.sync m16n8k16 bf16 (hi/lo split, 3 products, fp32).
//  - Embeddings (des/tweet, K=768 each) fused into one K=1536 HMMA kernel
//    with block-diagonal weights and zero-tile skipping.
//  - Graph aggregation: CSR over dst + warp-per-node gather, folded weights.
// ---------------------------------------------------------------------------
#define NMAX 100000
#define EMAX 600000

typedef unsigned long long ull;

// ------------------------- scratch (device globals) ------------------------
__device__ float g_bufA[(size_t)NMAX * 128];
__device__ float g_bufB[(size_t)NMAX * 128];
__device__ float g_y   [(size_t)NMAX * 384];   // [root | rel0 | rel1]

__device__ __nv_bfloat16 g_Whi[14 * 128 * 128]; // [mat][n][k]  (W^T, split hi)
__device__ __nv_bfloat16 g_Wlo[14 * 128 * 128]; // [mat][n][k]  (W^T, split lo)
__device__ __nv_bfloat16 g_Ehi[64 * 1536];      // embedding W, block-diag
__device__ __nv_bfloat16 g_Elo[64 * 1536];

__device__ int g_c0[NMAX];
__device__ int g_c1[NMAX];
__device__ int g_rp[NMAX + 1];
__device__ int g_cur[NMAX];
__device__ int g_ep[EMAX];                     // (src<<1)|rel
__device__ int g_bsum[128];
__device__ int g_boff[128];

// ------------------------------ small helpers ------------------------------
__device__ __forceinline__ float lrelu(float v) { return fmaxf(v, 0.01f * v); }

__device__ __forceinline__ void mma16816(float* c, const uint32_t* a,
                                         uint32_t b0, uint32_t b1) {
    asm volatile(
        "mma.sync.aligned.m16n8k16.row.col.f32.bf16.bf16.f32 "
        "{%0,%1,%2,%3}, {%4,%5,%6,%7}, {%8,%9}, {%0,%1,%2,%3};"
        : "+f"(c[0]), "+f"(c[1]), "+f"(c[2]), "+f"(c[3])
        : "r"(a[0]), "r"(a[1]), "r"(a[2]), "r"(a[3]), "r"(b0), "r"(b1));
}

// ------------------------------- weight prep -------------------------------
// g_Whi/g_Wlo[m][n][k] = split(bf16) of W_m[k][n]   (B col-major for mma)
__global__ void k_wprep(const float* __restrict__ Win,
                        const float* __restrict__ Wroot,
                        const float* __restrict__ Wrel,
                        const float* __restrict__ Wo1) {
    int idx = blockIdx.x * blockDim.x + threadIdx.x;
    if (idx >= 14 * 16384) return;
    int m = idx >> 14;
    int r = idx & 16383;
    int n = r >> 7, k = r & 127;
    const float* src;
    if (m == 0) src = Win;
    else if (m == 13) src = Wo1;
    else {
        int l = (m - 1) / 3, j = (m - 1) % 3;
        src = (j == 0) ? (Wroot + (size_t)l * 16384)
                       : (Wrel + (size_t)(l * 2 + (j - 1)) * 16384);
    }
    float v = src[k * 128 + n];
    __nv_bfloat16 h = __float2bfloat16(v);
    g_Whi[idx] = h;
    g_Wlo[idx] = __float2bfloat16(v - __bfloat162float(h));
}

// embedding combined weight: [64 n][1536 k] block-diagonal:
//   n<28, k<768   : W_des[k][n]
//   n>=28, k>=768 : W_tw[k-768][n-28]
//   else zero
__global__ void k_eprep(const float* __restrict__ Wd,
                        const float* __restrict__ Wt) {
    int idx = blockIdx.x * blockDim.x + threadIdx.x;
    if (idx >= 64 * 1536) return;
    int n = idx / 1536, k = idx % 1536;
    float v = 0.f;
    if (n < 28 && k < 768) v = Wd[k * 28 + n];
    else if (n >= 28 && k >= 768) v = Wt[(k - 768) * 36 + (n - 28)];
    __nv_bfloat16 h = __float2bfloat16(v);
    g_Ehi[idx] = h;
    g_Elo[idx] = __float2bfloat16(v - __bfloat162float(h));
}

// ----------------------- HMMA GEMM (bf16 split x3) -------------------------
// C[:, bIdx.y*128 ..] = act(A[M,128] @ W_mat + bias), row stride ldc.
// smem: bias(512B) | buf0(A hi, then A lo) | buf1(B hi) | buf2(B lo)
// row stride 136 bf16 = 272B (bank-conflict-free fragment loads).
#define MMS_BIAS 0
#define MMS_A    512
#define MMS_B1   35328
#define MMS_B2   70144
#define MMS_TOTAL 104960

// accumulate: acc += (smem A tile) @ (smem B tile)^T over K=128
__device__ __forceinline__ void mm_prod(const char* pa, const char* pb,
                                        int wm0, int wn0, int lane,
                                        float acc[2][8][4]) {
#pragma unroll
    for (int ks = 0; ks < 8; ks++) {
        uint32_t a[2][4];
#pragma unroll
        for (int mt = 0; mt < 2; mt++) {
            const char* ap = pa + (wm0 + mt * 16 + (lane >> 2)) * 272 +
                             (lane & 3) * 4 + ks * 32;
            a[mt][0] = *(const uint32_t*)ap;
            a[mt][1] = *(const uint32_t*)(ap + 8 * 272);
            a[mt][2] = *(const uint32_t*)(ap + 16);
            a[mt][3] = *(const uint32_t*)(ap + 8 * 272 + 16);
        }
#pragma unroll
        for (int nt = 0; nt < 8; nt++) {
            const char* bp = pb + (wn0 + nt * 8 + (lane >> 2)) * 272 +
                             (lane & 3) * 4 + ks * 32;
            uint32_t b0 = *(const uint32_t*)bp;
            uint32_t b1 = *(const uint32_t*)(bp + 16);
            mma16816(acc[0][nt], a[0], b0, b1);
            mma16816(acc[1][nt], a[1], b0, b1);
        }
    }
}

template <bool ACT>
__global__ void __launch_bounds__(256, 2)
mm_hmma(const float* __restrict__ A, int matBase,
        const float* __restrict__ bias, float* __restrict__ C,
        int M, int ldc) {
    extern __shared__ char sm[];
    float* sbias = (float*)(sm + MMS_BIAS);
    char* sA  = sm + MMS_A;
    char* sB1 = sm + MMS_B1;
    char* sB2 = sm + MMS_B2;

    int tid = threadIdx.x;
    int lane = tid & 31, wid = tid >> 5;
    int m0 = blockIdx.x * 128;
    int mat = matBase + blockIdx.y;

    if (tid < 128)
        sbias[tid] = (bias != nullptr && blockIdx.y == 0) ? bias[tid] : 0.f;

    // A hi tile
    for (int t = tid; t < 2048; t += 256) {
        int row = t >> 4, cq = t & 15;
        int gr = m0 + row;
        float x[8];
#pragma unroll
        for (int i = 0; i < 8; i++) x[i] = 0.f;
        if (gr < M) {
            float4 a0 = *(const float4*)&A[(size_t)gr * 128 + cq * 8];
            float4 a1 = *(const float4*)&A[(size_t)gr * 128 + cq * 8 + 4];
            x[0] = a0.x; x[1] = a0.y; x[2] = a0.z; x[3] = a0.w;
            x[4] = a1.x; x[5] = a1.y; x[6] = a1.z; x[7] = a1.w;
        }
        __nv_bfloat16 h[8];
#pragma unroll
        for (int i = 0; i < 8; i++) h[i] = __float2bfloat16(x[i]);
        *(uint4*)(sA + row * 272 + cq * 16) = *(const uint4*)h;
    }
    // B hi/lo tiles
    {
        const uint4* srcH = (const uint4*)(g_Whi + (size_t)mat * 16384);
        const uint4* srcL = (const uint4*)(g_Wlo + (size_t)mat * 16384);
        for (int t = tid; t < 2048; t += 256) {
            int n = t >> 4, kq = t & 15;
            *(uint4*)(sB1 + n * 272 + kq * 16) = srcH[t];
            *(uint4*)(sB2 + n * 272 + kq * 16) = srcL[t];
        }
    }
    __syncthreads();

    int wm0 = (wid >> 1) * 32;
    int wn0 = (wid & 1) * 64;

    float acc[2][8][4];
#pragma unroll
    for (int mt = 0; mt < 2; mt++)
#pragma unroll
        for (int nt = 0; nt < 8; nt++)
#pragma unroll
            for (int q = 0; q < 4; q++) acc[mt][nt][q] = 0.f;

    mm_prod(sA, sB1, wm0, wn0, lane, acc);   // Ah * Bh
    mm_prod(sA, sB2, wm0, wn0, lane, acc);   // Ah * Bl
    __syncthreads();

    // overwrite sA with A lo
    for (int t = tid; t < 2048; t += 256) {
        int row = t >> 4, cq = t & 15;
        int gr = m0 + row;
        float x[8];
#pragma unroll
        for (int i = 0; i < 8; i++) x[i] = 0.f;
        if (gr < M) {
            float4 a0 = *(const float4*)&A[(size_t)gr * 128 + cq * 8];
            float4 a1 = *(const float4*)&A[(size_t)gr * 128 + cq * 8 + 4];
            x[0] = a0.x; x[1] = a0.y; x[2] = a0.z; x[3] = a0.w;
            x[4] = a1.x; x[5] = a1.y; x[6] = a1.z; x[7] = a1.w;
        }
        __nv_bfloat16 l[8];
#pragma unroll
        for (int i = 0; i < 8; i++) {
            __nv_bfloat16 h = __float2bfloat16(x[i]);
            l[i] = __float2bfloat16(x[i] - __bfloat162float(h));
        }
        *(uint4*)(sA + row * 272 + cq * 16) = *(const uint4*)l;
    }
    __syncthreads();

    mm_prod(sA, sB1, wm0, wn0, lane, acc);   // Al * Bh

    // epilogue
    float2 b2[8];
#pragma unroll
    for (int nt = 0; nt < 8; nt++) {
        int c = wn0 + nt * 8 + (lane & 3) * 2;
        b2[nt] = make_float2(sbias[c], sbias[c + 1]);
    }
    int coff = blockIdx.y * 128;
#pragma unroll
    for (int mt = 0; mt < 2; mt++) {
        int r0 = m0 + wm0 + mt * 16 + (lane >> 2);
#pragma unroll
        for (int nt = 0; nt < 8; nt++) {
            int c = coff + wn0 + nt * 8 + (lane & 3) * 2;
            if (r0 < M) {
                float2 o = make_float2(acc[mt][nt][0] + b2[nt].x,
                                       acc[mt][nt][1] + b2[nt].y);
                if (ACT) { o.x = lrelu(o.x); o.y = lrelu(o.y); }
                *(float2*)&C[(size_t)r0 * ldc + c] = o;
            }
            if (r0 + 8 < M) {
                float2 o = make_float2(acc[mt][nt][2] + b2[nt].x,
                                       acc[mt][nt][3] + b2[nt].y);
                if (ACT) { o.x = lrelu(o.x); o.y = lrelu(o.y); }
                *(float2*)&C[(size_t)(r0 + 8) * ldc + c] = o;
            }
        }
    }
}

// --------------------- HMMA embedding GEMM (K=1536 fused) ------------------
// C[:, 0..63] = lrelu([des|tweet] @ blockdiag(W_des, W_tw) + [b_des|b_tw])
// smem: bias 512B | Ahi 128x144 | Alo 128x144 | Bhi 64x144 | Blo 64x144
#define ES_BIAS 0
#define ES_AH   512
#define ES_AL   (512 + 18432)
#define ES_BH   (512 + 36864)
#define ES_BL   (512 + 36864 + 9216)
#define ES_TOTAL (512 + 36864 + 18432)   // 55808

template <int NT0, int NT1>
__device__ __forceinline__ void emb_tiles(const char* sAh, const char* sAl,
                                          const char* sBh, const char* sBl,
                                          int wid, int lane, float acc[8][4]) {
#pragma unroll
    for (int ks = 0; ks < 4; ks++) {
        uint32_t aoff = (uint32_t)((wid * 16 + (lane >> 2)) * 144 +
                                   (lane & 3) * 4 + ks * 32);
        uint32_t ah[4], al[4];
        ah[0] = *(const uint32_t*)(sAh + aoff);
        ah[1] = *(const uint32_t*)(sAh + aoff + 8 * 144);
        ah[2] = *(const uint32_t*)(sAh + aoff + 16);
        ah[3] = *(const uint32_t*)(sAh + aoff + 8 * 144 + 16);
        al[0] = *(const uint32_t*)(sAl + aoff);
        al[1] = *(const uint32_t*)(sAl + aoff + 8 * 144);
        al[2] = *(const uint32_t*)(sAl + aoff + 16);
        al[3] = *(const uint32_t*)(sAl + aoff + 8 * 144 + 16);
#pragma unroll
        for (int nt = NT0; nt < NT1; nt++) {
            uint32_t boff = (uint32_t)((nt * 8 + (lane >> 2)) * 144 +
                                       (lane & 3) * 4 + ks * 32);
            uint32_t bh0 = *(const uint32_t*)(sBh + boff);
            uint32_t bh1 = *(const uint32_t*)(sBh + boff + 16);
            uint32_t bl0 = *(const uint32_t*)(sBl + boff);
            uint32_t bl1 = *(const uint32_t*)(sBl + boff + 16);
            mma16816(acc[nt], ah, bh0, bh1);
            mma16816(acc[nt], ah, bl0, bl1);
            mma16816(acc[nt], al, bh0, bh1);
        }
    }
}

__global__ void __launch_bounds__(256, 3)
emb_hmma(const float* __restrict__ des, const float* __restrict__ tweet,
         const float* __restrict__ bd, const float* __restrict__ bt,
         float* __restrict__ C, int M) {
    extern __shared__ char sm[];
    float* sbias = (float*)(sm + ES_BIAS);
    char* sAh = sm + ES_AH;
    char* sAl = sm + ES_AL;
    char* sBh = sm + ES_BH;
    char* sBl = sm + ES_BL;

    int tid = threadIdx.x;
    int lane = tid & 31, wid = tid >> 5;
    int m0 = blockIdx.x * 128;

    if (tid < 64) sbias[tid] = (tid < 28) ? bd[tid] : bt[tid - 28];

    float acc[8][4];
#pragma unroll
    for (int nt = 0; nt < 8; nt++)
#pragma unroll
        for (int q = 0; q < 4; q++) acc[nt][q] = 0.f;

    for (int kc = 0; kc < 24; kc++) {
        const float* src = (kc < 12) ? des : tweet;
        int k0 = (kc < 12) ? kc * 64 : (kc - 12) * 64;
        // A chunk: 128 rows x 64 cols fp32 -> bf16 hi/lo
        for (int t = tid; t < 2048; t += 256) {
            int row = t >> 4, cq = t & 15;
            int gr = m0 + row;
            float4 v = make_float4(0.f, 0.f, 0.f, 0.f);
            if (gr < M)
                v = *(const float4*)&src[(size_t)gr * 768 + k0 + cq * 4];
            __nv_bfloat16 h[4], l[4];
            float xv[4] = {v.x, v.y, v.z, v.w};
#pragma unroll
            for (int i = 0; i < 4; i++) {
                h[i] = __float2bfloat16(xv[i]);
                l[i] = __float2bfloat16(xv[i] - __bfloat162float(h[i]));
            }
            *(uint2*)(sAh + row * 144 + cq * 8) = *(const uint2*)h;
            *(uint2*)(sAl + row * 144 + cq * 8) = *(const uint2*)l;
        }
        // B chunk: 64 n x 64 k bf16 hi/lo
        for (int t = tid; t < 512; t += 256) {
            int n = t >> 3, kb = t & 7;
            int ke = kc * 64 + kb * 8;
            *(uint4*)(sBh + n * 144 + kb * 16) =
                *(const uint4*)(g_Ehi + n * 1536 + ke);
            *(uint4*)(sBl + n * 144 + kb * 16) =
                *(const uint4*)(g_Elo + n * 1536 + ke);
        }
        __syncthreads();

        if (kc < 12)
            emb_tiles<0, 4>(sAh, sAl, sBh, sBl, wid, lane, acc);
        else
            emb_tiles<3, 8>(sAh, sAl, sBh, sBl, wid, lane, acc);
        __syncthreads();
    }

    // epilogue: bias + lrelu -> C cols 0..63 (row stride 128)
#pragma unroll
    for (int nt = 0; nt < 8; nt++) {
        int c = nt * 8 + (lane & 3) * 2;
        float2 b2 = make_float2(sbias[c], sbias[c + 1]);
        int r0 = m0 + wid * 16 + (lane >> 2);
        if (r0 < M) {
            float2 o = make_float2(lrelu(acc[nt][0] + b2.x),
                                   lrelu(acc[nt][1] + b2.y));
            *(float2*)&C[(size_t)r0 * 128 + c] = o;
        }
        if (r0 + 8 < M) {
            float2 o = make_float2(lrelu(acc[nt][2] + b2.x),
                                   lrelu(acc[nt][3] + b2.y));
            *(float2*)&C[(size_t)(r0 + 8) * 128 + c] = o;
        }
    }
}

// ------------------------------- CSR build ---------------------------------
__global__ void k_zero(int n) {
    int i = blockIdx.x * blockDim.x + threadIdx.x;
    if (i < n) { g_c0[i] = 0; g_c1[i] = 0; }
}

__global__ void k_hist(const int* __restrict__ ei, const int* __restrict__ et,
                       int nE) {
    int i = blockIdx.x * blockDim.x + threadIdx.x;
    if (i >= nE) return;
    int d = ei[nE + i];
    if (et[i]) atomicAdd(&g_c1[d], 1);
    else       atomicAdd(&g_c0[d], 1);
}

__global__ void k_scan1(int n) {
    int tid = threadIdx.x;
    int i = blockIdx.x * 1024 + tid;
    int v = (i < n) ? (g_c0[i] + g_c1[i]) : 0;
    int x = v;
    int lane = tid & 31, w = tid >> 5;
#pragma unroll
    for (int d = 1; d < 32; d <<= 1) {
        int t = __shfl_up_sync(0xffffffffu, x, d);
        if (lane >= d) x += t;
    }
    __shared__ int wt[32];
    if (lane == 31) wt[w] = x;
    __syncthreads();
    if (w == 0) {
        int y = wt[lane];
#pragma unroll
        for (int d = 1; d < 32; d <<= 1) {
            int t = __shfl_up_sync(0xffffffffu, y, d);
            if (lane >= d) y += t;
        }
        wt[lane] = y;
    }
    __syncthreads();
    int off = (w > 0) ? wt[w - 1] : 0;
    int inc = x + off;
    if (i < n) g_rp[i] = inc - v;
    if (tid == 1023) g_bsum[blockIdx.x] = inc;
}

__global__ void k_scan2(int nb, int n, int nE) {
    int t = threadIdx.x;
    int lane = t & 31, w = t >> 5;
    int v = (t < nb) ? g_bsum[t] : 0;
    int x = v;
#pragma unroll
    for (int d = 1; d < 32; d <<= 1) {
        int s = __shfl_up_sync(0xffffffffu, x, d);
        if (lane >= d) x += s;
    }
    __shared__ int wt[4];
    if (lane == 31) wt[w] = x;
    __syncthreads();
    int off = 0;
    for (int k = 0; k < w; k++) off += wt[k];
    g_boff[t] = x + off - v;
    if (t == 0) g_rp[n] = nE;
}

__global__ void k_scan3(int n) {
    int i = blockIdx.x * blockDim.x + threadIdx.x;
    if (i >= n) return;
    int v = g_rp[i] + g_boff[i >> 10];
    g_rp[i] = v;
    g_cur[i] = v;
}

__global__ void k_fill(const int* __restrict__ ei, const int* __restrict__ et,
                       int nE) {
    int i = blockIdx.x * blockDim.x + threadIdx.x;
    if (i >= nE) return;
    int d = ei[nE + i];
    int pos = atomicAdd(&g_cur[d], 1);
    g_ep[pos] = (ei[i] << 1) | (et[i] ? 1 : 0);
}

// --------------------------- small embeddings ------------------------------
__global__ void k_small(const float* __restrict__ num,
                        const float* __restrict__ cat,
                        const float* __restrict__ nf,
                        const float* __restrict__ Wn, const float* __restrict__ bn,
                        const float* __restrict__ Wc, const float* __restrict__ bc,
                        const float* __restrict__ Ww, const float* __restrict__ bw,
                        float* __restrict__ xcat, int n) {
    int g = blockIdx.x * blockDim.x + threadIdx.x;
    if (g >= n * 64) return;
    int i = g >> 6, j = g & 63;
    float v;
    if (j < 12) {
        float s = bn[j];
#pragma unroll
        for (int k = 0; k < 7; k++)
            s = fmaf(num[(size_t)i * 7 + k], Wn[k * 12 + j], s);
        v = s;
    } else if (j < 52) {
        int c = j - 12;
        float s = bc[c];
#pragma unroll
        for (int k = 0; k < 11; k++)
            s = fmaf(cat[(size_t)i * 11 + k], Wc[k * 40 + c], s);
        v = s;
    } else {
        int c = j - 52;
        v = fmaf(nf[i], Ww[c], bw[c]);
    }
    xcat[(size_t)i * 128 + 64 + j] = lrelu(v);
}

// --------------------------- RGCN mean aggregation -------------------------
__global__ void k_agg(const float* __restrict__ y, float* __restrict__ out,
                      int n) {
    int g = blockIdx.x * blockDim.x + threadIdx.x;
    int gw = g >> 5;
    if (gw >= n) return;
    int lane = g & 31;
    int beg = g_rp[gw], end = g_rp[gw + 1];
    int c0 = g_c0[gw]; if (c0 < 1) c0 = 1;
    int c1 = g_c1[gw]; if (c1 < 1) c1 = 1;
    float w0 = 1.f / (float)c0;
    float w1 = 1.f / (float)c1;
    float4 o = ((const float4*)(y + (size_t)gw * 384))[lane];
    for (int e = beg; e < end; e++) {
        int p = g_ep[e];
        int r = p & 1;
        float wgt = r ? w1 : w0;
        const float4* v4 =
            (const float4*)(y + (size_t)(p >> 1) * 384 + 128 + (r << 7));
        float4 v = v4[lane];
        o.x = fmaf(v.x, wgt, o.x);
        o.y = fmaf(v.y, wgt, o.y);
        o.z = fmaf(v.z, wgt, o.z);
        o.w = fmaf(v.w, wgt, o.w);
    }
    ((float4*)(out + (size_t)gw * 128))[lane] = o;
}

// ------------------------------ final linear -------------------------------
__global__ void k_final(const float* __restrict__ h, const float* __restrict__ W2,
                        const float* __restrict__ b2, float* __restrict__ out,
                        int n) {
    int g = blockIdx.x * blockDim.x + threadIdx.x;
    int gw = g >> 5;
    if (gw >= n) return;
    int lane = g & 31;
    const float* hr = h + (size_t)gw * 128;
    float a0 = 0.f, a1 = 0.f;
#pragma unroll
    for (int t = 0; t < 4; t++) {
        int k = lane + 32 * t;
        float hv = hr[k];
        float2 w = *(const float2*)&W2[k * 2];
        a0 = fmaf(hv, w.x, a0);
        a1 = fmaf(hv, w.y, a1);
    }
#pragma unroll
    for (int o = 16; o > 0; o >>= 1) {
        a0 += __shfl_xor_sync(0xffffffffu, a0, o);
        a1 += __shfl_xor_sync(0xffffffffu, a1, o);
    }
    if (lane == 0) {
        out[(size_t)gw * 2]     = a0 + b2[0];
        out[(size_t)gw * 2 + 1] = a1 + b2[1];
    }
}

// --------------------------------- launch ----------------------------------
extern "C" void kernel_launch(void* const* d_in, const int* in_sizes, int n_in,
                              void* d_out, int out_size) {
    const float* des    = (const float*)d_in[0];
    const float* tweet  = (const float*)d_in[1];
    const float* num    = (const float*)d_in[2];
    const float* cat    = (const float*)d_in[3];
    const float* nf     = (const float*)d_in[4];
    const int*   ei     = (const int*)  d_in[5];
    const int*   et     = (const int*)  d_in[6];
    const float* W_des  = (const float*)d_in[7];
    const float* b_des  = (const float*)d_in[8];
    const float* W_tw   = (const float*)d_in[9];
    const float* b_tw   = (const float*)d_in[10];
    const float* W_num  = (const float*)d_in[11];
    const float* b_num  = (const float*)d_in[12];
    const float* W_cat  = (const float*)d_in[13];
    const float* b_cat  = (const float*)d_in[14];
    const float* W_new  = (const float*)d_in[15];
    const float* b_new  = (const float*)d_in[16];
    const float* W_in   = (const float*)d_in[17];
    const float* b_in   = (const float*)d_in[18];
    const float* W_root = (const float*)d_in[19];
    const float* W_rel  = (const float*)d_in[20];
    const float* b_rg   = (const float*)d_in[21];
    const float* W_o1   = (const float*)d_in[22];
    const float* b_o1   = (const float*)d_in[23];
    const float* W_o2   = (const float*)d_in[24];
    const float* b_o2   = (const float*)d_in[25];

    int nN = in_sizes[0] / 768;
    int nE = in_sizes[6];
    if (nN > NMAX) nN = NMAX;
    if (nE > EMAX) nE = EMAX;

    float *bufA, *bufB, *bufY;
    cudaGetSymbolAddress((void**)&bufA, g_bufA);
    cudaGetSymbolAddress((void**)&bufB, g_bufB);
    cudaGetSymbolAddress((void**)&bufY, g_y);

    cudaFuncSetAttribute(mm_hmma<true>,
                         cudaFuncAttributeMaxDynamicSharedMemorySize, MMS_TOTAL);
    cudaFuncSetAttribute(mm_hmma<false>,
                         cudaFuncAttributeMaxDynamicSharedMemorySize, MMS_TOTAL);
    cudaFuncSetAttribute(emb_hmma,
                         cudaFuncAttributeMaxDynamicSharedMemorySize, ES_TOTAL);

    int gm     = (nN + 127) / 128;
    int gN256  = (nN + 255) / 256;
    int gE256  = (nE + 255) / 256;
    int gScan  = (nN + 1023) / 1024;
    int gWarpN = (nN * 32 + 255) / 256;

    // weight prep
    k_wprep<<<(14 * 16384 + 255) / 256, 256>>>(W_in, W_root, W_rel, W_o1);
    k_eprep<<<(64 * 1536 + 255) / 256, 256>>>(W_des, W_tw);

    // embeddings -> bufA
    k_small<<<(nN * 64 + 255) / 256, 256>>>(num, cat, nf, W_num, b_num,
                                            W_cat, b_cat, W_new, b_new,
                                            bufA, nN);
    emb_hmma<<<gm, 256, ES_TOTAL>>>(des, tweet, b_des, b_tw, bufA, nN);

    // W_in (HMMA): bufA -> bufB, lrelu
    mm_hmma<true><<<dim3(gm, 1), 256, MMS_TOTAL>>>(bufA, 0, b_in, bufB, nN, 128);

    // CSR over dst
    k_zero<<<gN256, 256>>>(nN);
    k_hist<<<gE256, 256>>>(ei, et, nE);
    k_scan1<<<gScan, 1024>>>(nN);
    k_scan2<<<1, 128>>>(gScan, nN, nE);
    k_scan3<<<gN256, 256>>>(nN);
    k_fill<<<gE256, 256>>>(ei, et, nE);

    // 4 RGCN layers: x -> y[root|rel0|rel1] (HMMA, grid.y=3) -> aggregate
    float* x  = bufB;
    float* xn = bufA;
    for (int l = 0; l < 4; l++) {
        mm_hmma<false><<<dim3(gm, 3), 256, MMS_TOTAL>>>(
            x, 1 + 3 * l, b_rg + (size_t)l * 128, bufY, nN, 384);
        k_agg<<<gWarpN, 256>>>(bufY, xn, nN);
        float* t = x; x = xn; xn = t;
    }
    // after 4 swaps: x == bufB

    // W_o1 (HMMA): x -> bufA, lrelu
    mm_hmma<true><<<dim3(gm, 1), 256, MMS_TOTAL>>>(x, 13, b_o1, bufA, nN, 128);

    // final [N,2]
    k_final<<<gWarpN, 256>>>(bufA, W_o2, b_o2, (float*)d_out, nN);
}

// round 12
// speedup vs baseline: 2.8438x; 1.2649x over previous
#include <cuda_runtime.h>
#include <cuda_bf16.h>
#include <cstdint>

// ---------------------------------------------------------------------------
// ESABotRGCN 4-layer pipeline.
//  - All large GEMMs: mma.sync m16n8k16 bf16 (hi/lo split, 3 products, fp32).
//  - Embeddings: fused K=1536 HMMA kernel, register-staged prefetch pipeline.
//  - RGCN layer: aggregate-first (mean commutes with linear map), then one
//    fused K=384 GEMM: out = x@Wr + z0@W0 + z1@W1 + b.  No y buffer.
// ---------------------------------------------------------------------------
#define NMAX 100000
#define EMAX 600000

typedef unsigned long long ull;

// ------------------------- scratch (device globals) ------------------------
__device__ float g_bufA[(size_t)NMAX * 128];
__device__ float g_bufB[(size_t)NMAX * 128];
__device__ float g_z   [(size_t)NMAX * 256];   // [z_rel0 | z_rel1]

__device__ __nv_bfloat16 g_Whi[14 * 128 * 128]; // [mat][n][k]  (W^T, split hi)
__device__ __nv_bfloat16 g_Wlo[14 * 128 * 128]; // [mat][n][k]  (W^T, split lo)
__device__ __nv_bfloat16 g_Ehi[64 * 1536];      // embedding W, block-diag
__device__ __nv_bfloat16 g_Elo[64 * 1536];

__device__ int g_c0[NMAX];
__device__ int g_c1[NMAX];
__device__ int g_rp[NMAX + 1];
__device__ int g_cur[NMAX];
__device__ int g_ep[EMAX];                     // (src<<1)|rel
__device__ int g_bsum[128];
__device__ int g_boff[128];

// ------------------------------ small helpers ------------------------------
__device__ __forceinline__ float lrelu(float v) { return fmaxf(v, 0.01f * v); }

__device__ __forceinline__ void mma16816(float* c, const uint32_t* a,
                                         uint32_t b0, uint32_t b1) {
    asm volatile(
        "mma.sync.aligned.m16n8k16.row.col.f32.bf16.bf16.f32 "
        "{%0,%1,%2,%3}, {%4,%5,%6,%7}, {%8,%9}, {%0,%1,%2,%3};"
        : "+f"(c[0]), "+f"(c[1]), "+f"(c[2]), "+f"(c[3])
        : "r"(a[0]), "r"(a[1]), "r"(a[2]), "r"(a[3]), "r"(b0), "r"(b1));
}

// ------------------------------- weight prep -------------------------------
__global__ void k_wprep(const float* __restrict__ Win,
                        const float* __restrict__ Wroot,
                        const float* __restrict__ Wrel,
                        const float* __restrict__ Wo1) {
    int idx = blockIdx.x * blockDim.x + threadIdx.x;
    if (idx >= 14 * 16384) return;
    int m = idx >> 14;
    int r = idx & 16383;
    int n = r >> 7, k = r & 127;
    const float* src;
    if (m == 0) src = Win;
    else if (m == 13) src = Wo1;
    else {
        int l = (m - 1) / 3, j = (m - 1) % 3;
        src = (j == 0) ? (Wroot + (size_t)l * 16384)
                       : (Wrel + (size_t)(l * 2 + (j - 1)) * 16384);
    }
    float v = src[k * 128 + n];
    __nv_bfloat16 h = __float2bfloat16(v);
    g_Whi[idx] = h;
    g_Wlo[idx] = __float2bfloat16(v - __bfloat162float(h));
}

__global__ void k_eprep(const float* __restrict__ Wd,
                        const float* __restrict__ Wt) {
    int idx = blockIdx.x * blockDim.x + threadIdx.x;
    if (idx >= 64 * 1536) return;
    int n = idx / 1536, k = idx % 1536;
    float v = 0.f;
    if (n < 28 && k < 768) v = Wd[k * 28 + n];
    else if (n >= 28 && k >= 768) v = Wt[(k - 768) * 36 + (n - 28)];
    __nv_bfloat16 h = __float2bfloat16(v);
    g_Ehi[idx] = h;
    g_Elo[idx] = __float2bfloat16(v - __bfloat162float(h));
}

// ----------------------- HMMA GEMM (single 128x128 mat) --------------------
#define MMS_BIAS 0
#define MMS_A    512
#define MMS_B1   35328
#define MMS_B2   70144
#define MMS_TOTAL 104960

__device__ __forceinline__ void mm_prod(const char* pa, const char* pb,
                                        int wm0, int wn0, int lane,
                                        float acc[2][8][4]) {
#pragma unroll
    for (int ks = 0; ks < 8; ks++) {
        uint32_t a[2][4];
#pragma unroll
        for (int mt = 0; mt < 2; mt++) {
            const char* ap = pa + (wm0 + mt * 16 + (lane >> 2)) * 272 +
                             (lane & 3) * 4 + ks * 32;
            a[mt][0] = *(const uint32_t*)ap;
            a[mt][1] = *(const uint32_t*)(ap + 8 * 272);
            a[mt][2] = *(const uint32_t*)(ap + 16);
            a[mt][3] = *(const uint32_t*)(ap + 8 * 272 + 16);
        }
#pragma unroll
        for (int nt = 0; nt < 8; nt++) {
            const char* bp = pb + (wn0 + nt * 8 + (lane >> 2)) * 272 +
                             (lane & 3) * 4 + ks * 32;
            uint32_t b0 = *(const uint32_t*)bp;
            uint32_t b1 = *(const uint32_t*)(bp + 16);
            mma16816(acc[0][nt], a[0], b0, b1);
            mma16816(acc[1][nt], a[1], b0, b1);
        }
    }
}

template <bool ACT>
__global__ void __launch_bounds__(256, 2)
mm_hmma(const float* __restrict__ A, int matBase,
        const float* __restrict__ bias, float* __restrict__ C,
        int M, int ldc) {
    extern __shared__ char sm[];
    float* sbias = (float*)(sm + MMS_BIAS);
    char* sA  = sm + MMS_A;
    char* sB1 = sm + MMS_B1;
    char* sB2 = sm + MMS_B2;

    int tid = threadIdx.x;
    int lane = tid & 31, wid = tid >> 5;
    int m0 = blockIdx.x * 128;
    int mat = matBase + blockIdx.y;

    if (tid < 128)
        sbias[tid] = (bias != nullptr && blockIdx.y == 0) ? bias[tid] : 0.f;

    for (int t = tid; t < 2048; t += 256) {
        int row = t >> 4, cq = t & 15;
        int gr = m0 + row;
        float x[8];
#pragma unroll
        for (int i = 0; i < 8; i++) x[i] = 0.f;
        if (gr < M) {
            float4 a0 = *(const float4*)&A[(size_t)gr * 128 + cq * 8];
            float4 a1 = *(const float4*)&A[(size_t)gr * 128 + cq * 8 + 4];
            x[0] = a0.x; x[1] = a0.y; x[2] = a0.z; x[3] = a0.w;
            x[4] = a1.x; x[5] = a1.y; x[6] = a1.z; x[7] = a1.w;
        }
        __nv_bfloat16 h[8];
#pragma unroll
        for (int i = 0; i < 8; i++) h[i] = __float2bfloat16(x[i]);
        *(uint4*)(sA + row * 272 + cq * 16) = *(const uint4*)h;
    }
    {
        const uint4* srcH = (const uint4*)(g_Whi + (size_t)mat * 16384);
        const uint4* srcL = (const uint4*)(g_Wlo + (size_t)mat * 16384);
        for (int t = tid; t < 2048; t += 256) {
            int n = t >> 4, kq = t & 15;
            *(uint4*)(sB1 + n * 272 + kq * 16) = srcH[t];
            *(uint4*)(sB2 + n * 272 + kq * 16) = srcL[t];
        }
    }
    __syncthreads();

    int wm0 = (wid >> 1) * 32;
    int wn0 = (wid & 1) * 64;

    float acc[2][8][4];
#pragma unroll
    for (int mt = 0; mt < 2; mt++)
#pragma unroll
        for (int nt = 0; nt < 8; nt++)
#pragma unroll
            for (int q = 0; q < 4; q++) acc[mt][nt][q] = 0.f;

    mm_prod(sA, sB1, wm0, wn0, lane, acc);
    mm_prod(sA, sB2, wm0, wn0, lane, acc);
    __syncthreads();

    for (int t = tid; t < 2048; t += 256) {
        int row = t >> 4, cq = t & 15;
        int gr = m0 + row;
        float x[8];
#pragma unroll
        for (int i = 0; i < 8; i++) x[i] = 0.f;
        if (gr < M) {
            float4 a0 = *(const float4*)&A[(size_t)gr * 128 + cq * 8];
            float4 a1 = *(const float4*)&A[(size_t)gr * 128 + cq * 8 + 4];
            x[0] = a0.x; x[1] = a0.y; x[2] = a0.z; x[3] = a0.w;
            x[4] = a1.x; x[5] = a1.y; x[6] = a1.z; x[7] = a1.w;
        }
        __nv_bfloat16 l[8];
#pragma unroll
        for (int i = 0; i < 8; i++) {
            __nv_bfloat16 h = __float2bfloat16(x[i]);
            l[i] = __float2bfloat16(x[i] - __bfloat162float(h));
        }
        *(uint4*)(sA + row * 272 + cq * 16) = *(const uint4*)l;
    }
    __syncthreads();

    mm_prod(sA, sB1, wm0, wn0, lane, acc);

    float2 b2[8];
#pragma unroll
    for (int nt = 0; nt < 8; nt++) {
        int c = wn0 + nt * 8 + (lane & 3) * 2;
        b2[nt] = make_float2(sbias[c], sbias[c + 1]);
    }
    int coff = blockIdx.y * 128;
#pragma unroll
    for (int mt = 0; mt < 2; mt++) {
        int r0 = m0 + wm0 + mt * 16 + (lane >> 2);
#pragma unroll
        for (int nt = 0; nt < 8; nt++) {
            int c = coff + wn0 + nt * 8 + (lane & 3) * 2;
            if (r0 < M) {
                float2 o = make_float2(acc[mt][nt][0] + b2[nt].x,
                                       acc[mt][nt][1] + b2[nt].y);
                if (ACT) { o.x = lrelu(o.x); o.y = lrelu(o.y); }
                *(float2*)&C[(size_t)r0 * ldc + c] = o;
            }
            if (r0 + 8 < M) {
                float2 o = make_float2(acc[mt][nt][2] + b2[nt].x,
                                       acc[mt][nt][3] + b2[nt].y);
                if (ACT) { o.x = lrelu(o.x); o.y = lrelu(o.y); }
                *(float2*)&C[(size_t)(r0 + 8) * ldc + c] = o;
            }
        }
    }
}

// ------------------ fused RGCN layer GEMM: K=384, 3 A-parts ----------------
// out = x@Wr + z0@W0 + z1@W1 + bias    (no activation)
// smem rows: 144B stride (64 k bf16 + pad).
#define LS_BIAS 0
#define LS_AH   512
#define LS_AL   (512 + 18432)
#define LS_BH   (512 + 2 * 18432)
#define LS_BL   (512 + 3 * 18432)
#define LS_TOTAL (512 + 4 * 18432)   // 74240

__global__ void __launch_bounds__(256, 2)
mm_layer(const float* __restrict__ x, const float* __restrict__ z,
         int matBase, const float* __restrict__ bias,
         float* __restrict__ C, int M) {
    extern __shared__ char sm[];
    float* sbias = (float*)(sm + LS_BIAS);
    char* sAh = sm + LS_AH;
    char* sAl = sm + LS_AL;
    char* sBh = sm + LS_BH;
    char* sBl = sm + LS_BL;

    int tid = threadIdx.x;
    int lane = tid & 31, wid = tid >> 5;
    int m0 = blockIdx.x * 128;

    if (tid < 128) sbias[tid] = bias[tid];

    int wm0 = (wid >> 1) * 32;
    int wn0 = (wid & 1) * 64;

    float acc[2][8][4];
#pragma unroll
    for (int mt = 0; mt < 2; mt++)
#pragma unroll
        for (int nt = 0; nt < 8; nt++)
#pragma unroll
            for (int q = 0; q < 4; q++) acc[mt][nt][q] = 0.f;

    for (int c = 0; c < 6; c++) {
        int p = c >> 1, h = c & 1;
        const float* src = (p == 0) ? x : z;
        int rstride = (p == 0) ? 128 : 256;
        int coloff = (p == 0) ? h * 64 : (p - 1) * 128 + h * 64;

        // A chunk: 128 rows x 64 cols fp32 -> bf16 hi/lo
        for (int t = tid; t < 2048; t += 256) {
            int row = t >> 4, cq = t & 15;
            int gr = m0 + row;
            float4 v = make_float4(0.f, 0.f, 0.f, 0.f);
            if (gr < M)
                v = *(const float4*)&src[(size_t)gr * rstride + coloff + cq * 4];
            float xv[4] = {v.x, v.y, v.z, v.w};
            __nv_bfloat16 hh[4], ll[4];
#pragma unroll
            for (int i = 0; i < 4; i++) {
                hh[i] = __float2bfloat16(xv[i]);
                ll[i] = __float2bfloat16(xv[i] - __bfloat162float(hh[i]));
            }
            *(uint2*)(sAh + row * 144 + cq * 8) = *(const uint2*)hh;
            *(uint2*)(sAl + row * 144 + cq * 8) = *(const uint2*)ll;
        }
        // B chunk: 128 n x 64 k bf16 hi/lo
        {
            const __nv_bfloat16* bh =
                g_Whi + (size_t)(matBase + p) * 16384 + h * 64;
            const __nv_bfloat16* bl =
                g_Wlo + (size_t)(matBase + p) * 16384 + h * 64;
            for (int t = tid; t < 1024; t += 256) {
                int n = t >> 3, kb = t & 7;
                *(uint4*)(sBh + n * 144 + kb * 16) =
                    *(const uint4*)(bh + n * 128 + kb * 8);
                *(uint4*)(sBl + n * 144 + kb * 16) =
                    *(const uint4*)(bl + n * 128 + kb * 8);
            }
        }
        __syncthreads();

#pragma unroll
        for (int ks = 0; ks < 4; ks++) {
            uint32_t ah[2][4], al[2][4];
#pragma unroll
            for (int mt = 0; mt < 2; mt++) {
                uint32_t ao = (uint32_t)((wm0 + mt * 16 + (lane >> 2)) * 144 +
                                         (lane & 3) * 4 + ks * 32);
                ah[mt][0] = *(const uint32_t*)(sAh + ao);
                ah[mt][1] = *(const uint32_t*)(sAh + ao + 8 * 144);
                ah[mt][2] = *(const uint32_t*)(sAh + ao + 16);
                ah[mt][3] = *(const uint32_t*)(sAh + ao + 8 * 144 + 16);
                al[mt][0] = *(const uint32_t*)(sAl + ao);
                al[mt][1] = *(const uint32_t*)(sAl + ao + 8 * 144);
                al[mt][2] = *(const uint32_t*)(sAl + ao + 16);
                al[mt][3] = *(const uint32_t*)(sAl + ao + 8 * 144 + 16);
            }
#pragma unroll
            for (int nt = 0; nt < 8; nt++) {
                uint32_t bo = (uint32_t)((wn0 + nt * 8 + (lane >> 2)) * 144 +
                                         (lane & 3) * 4 + ks * 32);
                uint32_t bh0 = *(const uint32_t*)(sBh + bo);
                uint32_t bh1 = *(const uint32_t*)(sBh + bo + 16);
                uint32_t bl0 = *(const uint32_t*)(sBl + bo);
                uint32_t bl1 = *(const uint32_t*)(sBl + bo + 16);
#pragma unroll
                for (int mt = 0; mt < 2; mt++) {
                    mma16816(acc[mt][nt], ah[mt], bh0, bh1);
                    mma16816(acc[mt][nt], ah[mt], bl0, bl1);
                    mma16816(acc[mt][nt], al[mt], bh0, bh1);
                }
            }
        }
        __syncthreads();
    }

    // epilogue: + bias, no act
#pragma unroll
    for (int mt = 0; mt < 2; mt++) {
        int r0 = m0 + wm0 + mt * 16 + (lane >> 2);
#pragma unroll
        for (int nt = 0; nt < 8; nt++) {
            int cc = wn0 + nt * 8 + (lane & 3) * 2;
            float2 b2 = make_float2(sbias[cc], sbias[cc + 1]);
            if (r0 < M) {
                float2 o = make_float2(acc[mt][nt][0] + b2.x,
                                       acc[mt][nt][1] + b2.y);
                *(float2*)&C[(size_t)r0 * 128 + cc] = o;
            }
            if (r0 + 8 < M) {
                float2 o = make_float2(acc[mt][nt][2] + b2.x,
                                       acc[mt][nt][3] + b2.y);
                *(float2*)&C[(size_t)(r0 + 8) * 128 + cc] = o;
            }
        }
    }
}

// --------------------- HMMA embedding GEMM (K=1536 fused) ------------------
#define ES_BIAS 0
#define ES_AH   512
#define ES_AL   (512 + 18432)
#define ES_BH   (512 + 36864)
#define ES_BL   (512 + 36864 + 9216)
#define ES_TOTAL (512 + 36864 + 18432)   // 55808

template <int NT0, int NT1>
__device__ __forceinline__ void emb_tiles(const char* sAh, const char* sAl,
                                          const char* sBh, const char* sBl,
                                          int wid, int lane, float acc[8][4]) {
#pragma unroll
    for (int ks = 0; ks < 4; ks++) {
        uint32_t aoff = (uint32_t)((wid * 16 + (lane >> 2)) * 144 +
                                   (lane & 3) * 4 + ks * 32);
        uint32_t ah[4], al[4];
        ah[0] = *(const uint32_t*)(sAh + aoff);
        ah[1] = *(const uint32_t*)(sAh + aoff + 8 * 144);
        ah[2] = *(const uint32_t*)(sAh + aoff + 16);
        ah[3] = *(const uint32_t*)(sAh + aoff + 8 * 144 + 16);
        al[0] = *(const uint32_t*)(sAl + aoff);
        al[1] = *(const uint32_t*)(sAl + aoff + 8 * 144);
        al[2] = *(const uint32_t*)(sAl + aoff + 16);
        al[3] = *(const uint32_t*)(sAl + aoff + 8 * 144 + 16);
#pragma unroll
        for (int nt = NT0; nt < NT1; nt++) {
            uint32_t boff = (uint32_t)((nt * 8 + (lane >> 2)) * 144 +
                                       (lane & 3) * 4 + ks * 32);
            uint32_t bh0 = *(const uint32_t*)(sBh + boff);
            uint32_t bh1 = *(const uint32_t*)(sBh + boff + 16);
            uint32_t bl0 = *(const uint32_t*)(sBl + boff);
            uint32_t bl1 = *(const uint32_t*)(sBl + boff + 16);
            mma16816(acc[nt], ah, bh0, bh1);
            mma16816(acc[nt], ah, bl0, bl1);
            mma16816(acc[nt], al, bh0, bh1);
        }
    }
}

__global__ void __launch_bounds__(256, 2)
emb_hmma(const float* __restrict__ des, const float* __restrict__ tweet,
         const float* __restrict__ bd, const float* __restrict__ bt,
         float* __restrict__ C, int M) {
    extern __shared__ char sm[];
    float* sbias = (float*)(sm + ES_BIAS);
    char* sAh = sm + ES_AH;
    char* sAl = sm + ES_AL;
    char* sBh = sm + ES_BH;
    char* sBl = sm + ES_BL;

    int tid = threadIdx.x;
    int lane = tid & 31, wid = tid >> 5;
    int m0 = blockIdx.x * 128;

    if (tid < 64) sbias[tid] = (tid < 28) ? bd[tid] : bt[tid - 28];

    float acc[8][4];
#pragma unroll
    for (int nt = 0; nt < 8; nt++)
#pragma unroll
        for (int q = 0; q < 4; q++) acc[nt][q] = 0.f;

    // register staging: 8 float4 per thread = one 128x64 chunk across block
    float4 stage[8];
    {
        // preload chunk 0 (des, k0=0)
#pragma unroll
        for (int i = 0; i < 8; i++) {
            int t = tid + i * 256;
            int row = t >> 4, cq = t & 15;
            int gr = m0 + row;
            stage[i] = make_float4(0.f, 0.f, 0.f, 0.f);
            if (gr < M)
                stage[i] = *(const float4*)&des[(size_t)gr * 768 + cq * 4];
        }
    }

    for (int kc = 0; kc < 24; kc++) {
        // store staged A chunk -> smem hi/lo
#pragma unroll
        for (int i = 0; i < 8; i++) {
            int t = tid + i * 256;
            int row = t >> 4, cq = t & 15;
            float4 v = stage[i];
            float xv[4] = {v.x, v.y, v.z, v.w};
            __nv_bfloat16 h[4], l[4];
#pragma unroll
            for (int q = 0; q < 4; q++) {
                h[q] = __float2bfloat16(xv[q]);
                l[q] = __float2bfloat16(xv[q] - __bfloat162float(h[q]));
            }
            *(uint2*)(sAh + row * 144 + cq * 8) = *(const uint2*)h;
            *(uint2*)(sAl + row * 144 + cq * 8) = *(const uint2*)l;
        }
        // B chunk
        for (int t = tid; t < 512; t += 256) {
            int n = t >> 3, kb = t & 7;
            int ke = kc * 64 + kb * 8;
            *(uint4*)(sBh + n * 144 + kb * 16) =
                *(const uint4*)(g_Ehi + n * 1536 + ke);
            *(uint4*)(sBl + n * 144 + kb * 16) =
                *(const uint4*)(g_Elo + n * 1536 + ke);
        }
        __syncthreads();

        // issue next chunk's global loads (hidden under compute)
        if (kc < 23) {
            int kn = kc + 1;
            const float* src = (kn < 12) ? des : tweet;
            int k0 = (kn < 12) ? kn * 64 : (kn - 12) * 64;
#pragma unroll
            for (int i = 0; i < 8; i++) {
                int t = tid + i * 256;
                int row = t >> 4, cq = t & 15;
                int gr = m0 + row;
                stage[i] = make_float4(0.f, 0.f, 0.f, 0.f);
                if (gr < M)
                    stage[i] = *(const float4*)&src[(size_t)gr * 768 + k0 + cq * 4];
            }
        }

        if (kc < 12)
            emb_tiles<0, 4>(sAh, sAl, sBh, sBl, wid, lane, acc);
        else
            emb_tiles<3, 8>(sAh, sAl, sBh, sBl, wid, lane, acc);
        __syncthreads();
    }

    // epilogue
#pragma unroll
    for (int nt = 0; nt < 8; nt++) {
        int c = nt * 8 + (lane & 3) * 2;
        float2 b2 = make_float2(sbias[c], sbias[c + 1]);
        int r0 = m0 + wid * 16 + (lane >> 2);
        if (r0 < M) {
            float2 o = make_float2(lrelu(acc[nt][0] + b2.x),
                                   lrelu(acc[nt][1] + b2.y));
            *(float2*)&C[(size_t)r0 * 128 + c] = o;
        }
        if (r0 + 8 < M) {
            float2 o = make_float2(lrelu(acc[nt][2] + b2.x),
                                   lrelu(acc[nt][3] + b2.y));
            *(float2*)&C[(size_t)(r0 + 8) * 128 + c] = o;
        }
    }
}

// ------------------------------- CSR build ---------------------------------
__global__ void k_zero(int n) {
    int i = blockIdx.x * blockDim.x + threadIdx.x;
    if (i < n) { g_c0[i] = 0; g_c1[i] = 0; }
}

__global__ void k_hist(const int* __restrict__ ei, const int* __restrict__ et,
                       int nE) {
    int i = blockIdx.x * blockDim.x + threadIdx.x;
    if (i >= nE) return;
    int d = ei[nE + i];
    if (et[i]) atomicAdd(&g_c1[d], 1);
    else       atomicAdd(&g_c0[d], 1);
}

__global__ void k_scan1(int n) {
    int tid = threadIdx.x;
    int i = blockIdx.x * 1024 + tid;
    int v = (i < n) ? (g_c0[i] + g_c1[i]) : 0;
    int x = v;
    int lane = tid & 31, w = tid >> 5;
#pragma unroll
    for (int d = 1; d < 32; d <<= 1) {
        int t = __shfl_up_sync(0xffffffffu, x, d);
        if (lane >= d) x += t;
    }
    __shared__ int wt[32];
    if (lane == 31) wt[w] = x;
    __syncthreads();
    if (w == 0) {
        int y = wt[lane];
#pragma unroll
        for (int d = 1; d < 32; d <<= 1) {
            int t = __shfl_up_sync(0xffffffffu, y, d);
            if (lane >= d) y += t;
        }
        wt[lane] = y;
    }
    __syncthreads();
    int off = (w > 0) ? wt[w - 1] : 0;
    int inc = x + off;
    if (i < n) g_rp[i] = inc - v;
    if (tid == 1023) g_bsum[blockIdx.x] = inc;
}

__global__ void k_scan2(int nb, int n, int nE) {
    int t = threadIdx.x;
    int lane = t & 31, w = t >> 5;
    int v = (t < nb) ? g_bsum[t] : 0;
    int x = v;
#pragma unroll
    for (int d = 1; d < 32; d <<= 1) {
        int s = __shfl_up_sync(0xffffffffu, x, d);
        if (lane >= d) x += s;
    }
    __shared__ int wt[4];
    if (lane == 31) wt[w] = x;
    __syncthreads();
    int off = 0;
    for (int k = 0; k < w; k++) off += wt[k];
    g_boff[t] = x + off - v;
    if (t == 0) g_rp[n] = nE;
}

__global__ void k_scan3(int n) {
    int i = blockIdx.x * blockDim.x + threadIdx.x;
    if (i >= n) return;
    int v = g_rp[i] + g_boff[i >> 10];
    g_rp[i] = v;
    g_cur[i] = v;
}

__global__ void k_fill(const int* __restrict__ ei, const int* __restrict__ et,
                       int nE) {
    int i = blockIdx.x * blockDim.x + threadIdx.x;
    if (i >= nE) return;
    int d = ei[nE + i];
    int pos = atomicAdd(&g_cur[d], 1);
    g_ep[pos] = (ei[i] << 1) | (et[i] ? 1 : 0);
}

// --------------------------- small embeddings ------------------------------
__global__ void k_small(const float* __restrict__ num,
                        const float* __restrict__ cat,
                        const float* __restrict__ nf,
                        const float* __restrict__ Wn, const float* __restrict__ bn,
                        const float* __restrict__ Wc, const float* __restrict__ bc,
                        const float* __restrict__ Ww, const float* __restrict__ bw,
                        float* __restrict__ xcat, int n) {
    int g = blockIdx.x * blockDim.x + threadIdx.x;
    if (g >= n * 64) return;
    int i = g >> 6, j = g & 63;
    float v;
    if (j < 12) {
        float s = bn[j];
#pragma unroll
        for (int k = 0; k < 7; k++)
            s = fmaf(num[(size_t)i * 7 + k], Wn[k * 12 + j], s);
        v = s;
    } else if (j < 52) {
        int c = j - 12;
        float s = bc[c];
#pragma unroll
        for (int k = 0; k < 11; k++)
            s = fmaf(cat[(size_t)i * 11 + k], Wc[k * 40 + c], s);
        v = s;
    } else {
        int c = j - 52;
        v = fmaf(nf[i], Ww[c], bw[c]);
    }
    xcat[(size_t)i * 128 + 64 + j] = lrelu(v);
}

// --------------------- pre-aggregation: z_r = mean_r(x_src) ----------------
__global__ void k_agg2(const float* __restrict__ x, float* __restrict__ z,
                       int n) {
    int g = blockIdx.x * blockDim.x + threadIdx.x;
    int gw = g >> 5;
    if (gw >= n) return;
    int lane = g & 31;
    int beg = g_rp[gw], end = g_rp[gw + 1];
    int c0 = g_c0[gw]; if (c0 < 1) c0 = 1;
    int c1 = g_c1[gw]; if (c1 < 1) c1 = 1;
    float w0 = 1.f / (float)c0;
    float w1 = 1.f / (float)c1;
    float4 a0 = make_float4(0.f, 0.f, 0.f, 0.f);
    float4 a1 = make_float4(0.f, 0.f, 0.f, 0.f);
    for (int e = beg; e < end; e++) {
        int p = g_ep[e];
        float4 v = ((const float4*)(x + (size_t)(p >> 1) * 128))[lane];
        if (p & 1) { a1.x += v.x; a1.y += v.y; a1.z += v.z; a1.w += v.w; }
        else       { a0.x += v.x; a0.y += v.y; a0.z += v.z; a0.w += v.w; }
    }
    a0.x *= w0; a0.y *= w0; a0.z *= w0; a0.w *= w0;
    a1.x *= w1; a1.y *= w1; a1.z *= w1; a1.w *= w1;
    ((float4*)(z + (size_t)gw * 256))[lane] = a0;
    ((float4*)(z + (size_t)gw * 256 + 128))[lane] = a1;
}

// ------------------------------ final linear -------------------------------
__global__ void k_final(const float* __restrict__ h, const float* __restrict__ W2,
                        const float* __restrict__ b2, float* __restrict__ out,
                        int n) {
    int g = blockIdx.x * blockDim.x + threadIdx.x;
    int gw = g >> 5;
    if (gw >= n) return;
    int lane = g & 31;
    const float* hr = h + (size_t)gw * 128;
    float a0 = 0.f, a1 = 0.f;
#pragma unroll
    for (int t = 0; t < 4; t++) {
        int k = lane + 32 * t;
        float hv = hr[k];
        float2 w = *(const float2*)&W2[k * 2];
        a0 = fmaf(hv, w.x, a0);
        a1 = fmaf(hv, w.y, a1);
    }
#pragma unroll
    for (int o = 16; o > 0; o >>= 1) {
        a0 += __shfl_xor_sync(0xffffffffu, a0, o);
        a1 += __shfl_xor_sync(0xffffffffu, a1, o);
    }
    if (lane == 0) {
        out[(size_t)gw * 2]     = a0 + b2[0];
        out[(size_t)gw * 2 + 1] = a1 + b2[1];
    }
}

// --------------------------------- launch ----------------------------------
extern "C" void kernel_launch(void* const* d_in, const int* in_sizes, int n_in,
                              void* d_out, int out_size) {
    const float* des    = (const float*)d_in[0];
    const float* tweet  = (const float*)d_in[1];
    const float* num    = (const float*)d_in[2];
    const float* cat    = (const float*)d_in[3];
    const float* nf     = (const float*)d_in[4];
    const int*   ei     = (const int*)  d_in[5];
    const int*   et     = (const int*)  d_in[6];
    const float* W_des  = (const float*)d_in[7];
    const float* b_des  = (const float*)d_in[8];
    const float* W_tw   = (const float*)d_in[9];
    const float* b_tw   = (const float*)d_in[10];
    const float* W_num  = (const float*)d_in[11];
    const float* b_num  = (const float*)d_in[12];
    const float* W_cat  = (const float*)d_in[13];
    const float* b_cat  = (const float*)d_in[14];
    const float* W_new  = (const float*)d_in[15];
    const float* b_new  = (const float*)d_in[16];
    const float* W_in   = (const float*)d_in[17];
    const float* b_in   = (const float*)d_in[18];
    const float* W_root = (const float*)d_in[19];
    const float* W_rel  = (const float*)d_in[20];
    const float* b_rg   = (const float*)d_in[21];
    const float* W_o1   = (const float*)d_in[22];
    const float* b_o1   = (const float*)d_in[23];
    const float* W_o2   = (const float*)d_in[24];
    const float* b_o2   = (const float*)d_in[25];

    int nN = in_sizes[0] / 768;
    int nE = in_sizes[6];
    if (nN > NMAX) nN = NMAX;
    if (nE > EMAX) nE = EMAX;

    float *bufA, *bufB, *bufZ;
    cudaGetSymbolAddress((void**)&bufA, g_bufA);
    cudaGetSymbolAddress((void**)&bufB, g_bufB);
    cudaGetSymbolAddress((void**)&bufZ, g_z);

    cudaFuncSetAttribute(mm_hmma<true>,
                         cudaFuncAttributeMaxDynamicSharedMemorySize, MMS_TOTAL);
    cudaFuncSetAttribute(mm_layer,
                         cudaFuncAttributeMaxDynamicSharedMemorySize, LS_TOTAL);
    cudaFuncSetAttribute(emb_hmma,
                         cudaFuncAttributeMaxDynamicSharedMemorySize, ES_TOTAL);

    int gm     = (nN + 127) / 128;
    int gN256  = (nN + 255) / 256;
    int gE256  = (nE + 255) / 256;
    int gScan  = (nN + 1023) / 1024;
    int gWarpN = (nN * 32 + 255) / 256;

    // weight prep
    k_wprep<<<(14 * 16384 + 255) / 256, 256>>>(W_in, W_root, W_rel, W_o1);
    k_eprep<<<(64 * 1536 + 255) / 256, 256>>>(W_des, W_tw);

    // embeddings -> bufA
    k_small<<<(nN * 64 + 255) / 256, 256>>>(num, cat, nf, W_num, b_num,
                                            W_cat, b_cat, W_new, b_new,
                                            bufA, nN);
    emb_hmma<<<gm, 256, ES_TOTAL>>>(des, tweet, b_des, b_tw, bufA, nN);

    // W_in (HMMA): bufA -> bufB, lrelu
    mm_hmma<true><<<dim3(gm, 1), 256, MMS_TOTAL>>>(bufA, 0, b_in, bufB, nN, 128);

    // CSR over dst
    k_zero<<<gN256, 256>>>(nN);
    k_hist<<<gE256, 256>>>(ei, et, nE);
    k_scan1<<<gScan, 1024>>>(nN);
    k_scan2<<<1, 128>>>(gScan, nN, nE);
    k_scan3<<<gN256, 256>>>(nN);
    k_fill<<<gE256, 256>>>(ei, et, nE);

    // 4 RGCN layers: aggregate x first, then fused K=384 GEMM
    float* x  = bufB;
    float* xn = bufA;
    for (int l = 0; l < 4; l++) {
        k_agg2<<<gWarpN, 256>>>(x, bufZ, nN);
        mm_layer<<<gm, 256, LS_TOTAL>>>(x, bufZ, 1 + 3 * l,
                                        b_rg + (size_t)l * 128, xn, nN);
        float* t = x; x = xn; xn = t;
    }
    // after 4 swaps: x == bufB

    // W_o1 (HMMA): x -> bufA, lrelu
    mm_hmma<true><<<dim3(gm, 1), 256, MMS_TOTAL>>>(x, 13, b_o1, bufA, nN, 128);

    // final [N,2]
    k_final<<<gWarpN, 256>>>(bufA, W_o2, b_o2, (float*)d_out, nN);
}

// round 13
// speedup vs baseline: 3.0055x; 1.0569x over previous
#include <cuda_runtime.h>
#include <cuda_bf16.h>
#include <cstdint>

// ---------------------------------------------------------------------------
// ESABotRGCN 4-layer pipeline.
//  - All large GEMMs: mma.sync m16n8k16 bf16 (hi/lo split, 3 products, fp32),
//    fragment loads via ldmatrix.
//  - Embeddings: fused K=1536 HMMA kernel with cp.async staging pipeline
//    (fp32 A stage + double-buffered bf16 B).
//  - RGCN layer: aggregate-first, then one fused K=384 GEMM.
// ---------------------------------------------------------------------------
#define NMAX 100000
#define EMAX 600000

typedef unsigned long long ull;

// ------------------------- scratch (device globals) ------------------------
__device__ float g_bufA[(size_t)NMAX * 128];
__device__ float g_bufB[(size_t)NMAX * 128];
__device__ float g_z   [(size_t)NMAX * 256];   // [z_rel0 | z_rel1]

__device__ __nv_bfloat16 g_Whi[14 * 128 * 128]; // [mat][n][k]  (W^T, split hi)
__device__ __nv_bfloat16 g_Wlo[14 * 128 * 128]; // [mat][n][k]  (W^T, split lo)
__device__ __nv_bfloat16 g_Ehi[64 * 1536];      // embedding W, block-diag
__device__ __nv_bfloat16 g_Elo[64 * 1536];

__device__ int g_c0[NMAX];
__device__ int g_c1[NMAX];
__device__ int g_rp[NMAX + 1];
__device__ int g_cur[NMAX];
__device__ int g_ep[EMAX];                     // (src<<1)|rel
__device__ int g_bsum[128];
__device__ int g_boff[128];

// ------------------------------ small helpers ------------------------------
__device__ __forceinline__ float lrelu(float v) { return fmaxf(v, 0.01f * v); }

__device__ __forceinline__ void mma16816(float* c, const uint32_t* a,
                                         uint32_t b0, uint32_t b1) {
    asm volatile(
        "mma.sync.aligned.m16n8k16.row.col.f32.bf16.bf16.f32 "
        "{%0,%1,%2,%3}, {%4,%5,%6,%7}, {%8,%9}, {%0,%1,%2,%3};"
        : "+f"(c[0]), "+f"(c[1]), "+f"(c[2]), "+f"(c[3])
        : "r"(a[0]), "r"(a[1]), "r"(a[2]), "r"(a[3]), "r"(b0), "r"(b1));
}

__device__ __forceinline__ void ldsm4(uint32_t* r, uint32_t a) {
    asm volatile("ldmatrix.sync.aligned.m8n8.x4.shared.b16 {%0,%1,%2,%3}, [%4];"
                 : "=r"(r[0]), "=r"(r[1]), "=r"(r[2]), "=r"(r[3]) : "r"(a));
}
__device__ __forceinline__ void ldsm2(uint32_t& r0, uint32_t& r1, uint32_t a) {
    asm volatile("ldmatrix.sync.aligned.m8n8.x2.shared.b16 {%0,%1}, [%2];"
                 : "=r"(r0), "=r"(r1) : "r"(a));
}

// ------------------------------- weight prep -------------------------------
__global__ void k_wprep(const float* __restrict__ Win,
                        const float* __restrict__ Wroot,
                        const float* __restrict__ Wrel,
                        const float* __restrict__ Wo1) {
    int idx = blockIdx.x * blockDim.x + threadIdx.x;
    if (idx >= 14 * 16384) return;
    int m = idx >> 14;
    int r = idx & 16383;
    int n = r >> 7, k = r & 127;
    const float* src;
    if (m == 0) src = Win;
    else if (m == 13) src = Wo1;
    else {
        int l = (m - 1) / 3, j = (m - 1) % 3;
        src = (j == 0) ? (Wroot + (size_t)l * 16384)
                       : (Wrel + (size_t)(l * 2 + (j - 1)) * 16384);
    }
    float v = src[k * 128 + n];
    __nv_bfloat16 h = __float2bfloat16(v);
    g_Whi[idx] = h;
    g_Wlo[idx] = __float2bfloat16(v - __bfloat162float(h));
}

__global__ void k_eprep(const float* __restrict__ Wd,
                        const float* __restrict__ Wt) {
    int idx = blockIdx.x * blockDim.x + threadIdx.x;
    if (idx >= 64 * 1536) return;
    int n = idx / 1536, k = idx % 1536;
    float v = 0.f;
    if (n < 28 && k < 768) v = Wd[k * 28 + n];
    else if (n >= 28 && k >= 768) v = Wt[(k - 768) * 36 + (n - 28)];
    __nv_bfloat16 h = __float2bfloat16(v);
    g_Ehi[idx] = h;
    g_Elo[idx] = __float2bfloat16(v - __bfloat162float(h));
}

// ----------------------- HMMA GEMM (single 128x128 mat) --------------------
#define MMS_BIAS 0
#define MMS_A    512
#define MMS_B1   35328
#define MMS_B2   70144
#define MMS_TOTAL 104960

__device__ __forceinline__ void mm_prod(uint32_t pa, uint32_t pb,
                                        int wm0, int wn0, int lane,
                                        float acc[2][8][4]) {
    int la = ((lane >> 3) & 1) * 8 + (lane & 7);
    int lc = (lane >> 4) * 16;
    int lb = lane & 7;
    int lbm = ((lane >> 3) & 1) * 16;
#pragma unroll
    for (int ks = 0; ks < 8; ks++) {
        uint32_t a[2][4];
#pragma unroll
        for (int mt = 0; mt < 2; mt++)
            ldsm4(a[mt], pa + (uint32_t)((wm0 + mt * 16 + la) * 272 +
                                         ks * 32 + lc));
#pragma unroll
        for (int nt = 0; nt < 8; nt++) {
            uint32_t b0, b1;
            ldsm2(b0, b1, pb + (uint32_t)((wn0 + nt * 8 + lb) * 272 +
                                          ks * 32 + lbm));
            mma16816(acc[0][nt], a[0], b0, b1);
            mma16816(acc[1][nt], a[1], b0, b1);
        }
    }
}

template <bool ACT>
__global__ void __launch_bounds__(256, 2)
mm_hmma(const float* __restrict__ A, int matBase,
        const float* __restrict__ bias, float* __restrict__ C,
        int M, int ldc) {
    extern __shared__ char sm[];
    float* sbias = (float*)(sm + MMS_BIAS);
    char* sA  = sm + MMS_A;
    char* sB1 = sm + MMS_B1;
    char* sB2 = sm + MMS_B2;
    uint32_t sb = (uint32_t)__cvta_generic_to_shared(sm);
    uint32_t uA = sb + MMS_A, uB1 = sb + MMS_B1, uB2 = sb + MMS_B2;

    int tid = threadIdx.x;
    int lane = tid & 31, wid = tid >> 5;
    int m0 = blockIdx.x * 128;
    int mat = matBase + blockIdx.y;

    if (tid < 128)
        sbias[tid] = (bias != nullptr && blockIdx.y == 0) ? bias[tid] : 0.f;

    for (int t = tid; t < 2048; t += 256) {
        int row = t >> 4, cq = t & 15;
        int gr = m0 + row;
        float x[8];
#pragma unroll
        for (int i = 0; i < 8; i++) x[i] = 0.f;
        if (gr < M) {
            float4 a0 = *(const float4*)&A[(size_t)gr * 128 + cq * 8];
            float4 a1 = *(const float4*)&A[(size_t)gr * 128 + cq * 8 + 4];
            x[0] = a0.x; x[1] = a0.y; x[2] = a0.z; x[3] = a0.w;
            x[4] = a1.x; x[5] = a1.y; x[6] = a1.z; x[7] = a1.w;
        }
        __nv_bfloat16 h[8];
#pragma unroll
        for (int i = 0; i < 8; i++) h[i] = __float2bfloat16(x[i]);
        *(uint4*)(sA + row * 272 + cq * 16) = *(const uint4*)h;
    }
    {
        const uint4* srcH = (const uint4*)(g_Whi + (size_t)mat * 16384);
        const uint4* srcL = (const uint4*)(g_Wlo + (size_t)mat * 16384);
        for (int t = tid; t < 2048; t += 256) {
            int n = t >> 4, kq = t & 15;
            *(uint4*)(sB1 + n * 272 + kq * 16) = srcH[t];
            *(uint4*)(sB2 + n * 272 + kq * 16) = srcL[t];
        }
    }
    __syncthreads();

    int wm0 = (wid >> 1) * 32;
    int wn0 = (wid & 1) * 64;

    float acc[2][8][4];
#pragma unroll
    for (int mt = 0; mt < 2; mt++)
#pragma unroll
        for (int nt = 0; nt < 8; nt++)
#pragma unroll
            for (int q = 0; q < 4; q++) acc[mt][nt][q] = 0.f;

    mm_prod(uA, uB1, wm0, wn0, lane, acc);
    mm_prod(uA, uB2, wm0, wn0, lane, acc);
    __syncthreads();

    for (int t = tid; t < 2048; t += 256) {
        int row = t >> 4, cq = t & 15;
        int gr = m0 + row;
        float x[8];
#pragma unroll
        for (int i = 0; i < 8; i++) x[i] = 0.f;
        if (gr < M) {
            float4 a0 = *(const float4*)&A[(size_t)gr * 128 + cq * 8];
            float4 a1 = *(const float4*)&A[(size_t)gr * 128 + cq * 8 + 4];
            x[0] = a0.x; x[1] = a0.y; x[2] = a0.z; x[3] = a0.w;
            x[4] = a1.x; x[5] = a1.y; x[6] = a1.z; x[7] = a1.w;
        }
        __nv_bfloat16 l[8];
#pragma unroll
        for (int i = 0; i < 8; i++) {
            __nv_bfloat16 h = __float2bfloat16(x[i]);
            l[i] = __float2bfloat16(x[i] - __bfloat162float(h));
        }
        *(uint4*)(sA + row * 272 + cq * 16) = *(const uint4*)l;
    }
    __syncthreads();

    mm_prod(uA, uB1, wm0, wn0, lane, acc);

    float2 b2[8];
#pragma unroll
    for (int nt = 0; nt < 8; nt++) {
        int c = wn0 + nt * 8 + (lane & 3) * 2;
        b2[nt] = make_float2(sbias[c], sbias[c + 1]);
    }
    int coff = blockIdx.y * 128;
#pragma unroll
    for (int mt = 0; mt < 2; mt++) {
        int r0 = m0 + wm0 + mt * 16 + (lane >> 2);
#pragma unroll
        for (int nt = 0; nt < 8; nt++) {
            int c = coff + wn0 + nt * 8 + (lane & 3) * 2;
            if (r0 < M) {
                float2 o = make_float2(acc[mt][nt][0] + b2[nt].x,
                                       acc[mt][nt][1] + b2[nt].y);
                if (ACT) { o.x = lrelu(o.x); o.y = lrelu(o.y); }
                *(float2*)&C[(size_t)r0 * ldc + c] = o;
            }
            if (r0 + 8 < M) {
                float2 o = make_float2(acc[mt][nt][2] + b2[nt].x,
                                       acc[mt][nt][3] + b2[nt].y);
                if (ACT) { o.x = lrelu(o.x); o.y = lrelu(o.y); }
                *(float2*)&C[(size_t)(r0 + 8) * ldc + c] = o;
            }
        }
    }
}

// ------------------ fused RGCN layer GEMM: K=384, 3 A-parts ----------------
#define LS_BIAS 0
#define LS_AH   512
#define LS_AL   (512 + 18432)
#define LS_BH   (512 + 2 * 18432)
#define LS_BL   (512 + 3 * 18432)
#define LS_TOTAL (512 + 4 * 18432)   // 74240

__global__ void __launch_bounds__(256, 2)
mm_layer(const float* __restrict__ x, const float* __restrict__ z,
         int matBase, const float* __restrict__ bias,
         float* __restrict__ C, int M) {
    extern __shared__ char sm[];
    float* sbias = (float*)(sm + LS_BIAS);
    char* sAh = sm + LS_AH;
    char* sAl = sm + LS_AL;
    char* sBh = sm + LS_BH;
    char* sBl = sm + LS_BL;
    uint32_t sb = (uint32_t)__cvta_generic_to_shared(sm);
    uint32_t uAh = sb + LS_AH, uAl = sb + LS_AL;
    uint32_t uBh = sb + LS_BH, uBl = sb + LS_BL;

    int tid = threadIdx.x;
    int lane = tid & 31, wid = tid >> 5;
    int m0 = blockIdx.x * 128;

    if (tid < 128) sbias[tid] = bias[tid];

    int wm0 = (wid >> 1) * 32;
    int wn0 = (wid & 1) * 64;
    int la = ((lane >> 3) & 1) * 8 + (lane & 7);
    int lc = (lane >> 4) * 16;
    int lb = lane & 7;
    int lbm = ((lane >> 3) & 1) * 16;

    float acc[2][8][4];
#pragma unroll
    for (int mt = 0; mt < 2; mt++)
#pragma unroll
        for (int nt = 0; nt < 8; nt++)
#pragma unroll
            for (int q = 0; q < 4; q++) acc[mt][nt][q] = 0.f;

    for (int c = 0; c < 6; c++) {
        int p = c >> 1, h = c & 1;
        const float* src = (p == 0) ? x : z;
        int rstride = (p == 0) ? 128 : 256;
        int coloff = (p == 0) ? h * 64 : (p - 1) * 128 + h * 64;

        for (int t = tid; t < 2048; t += 256) {
            int row = t >> 4, cq = t & 15;
            int gr = m0 + row;
            float4 v = make_float4(0.f, 0.f, 0.f, 0.f);
            if (gr < M)
                v = *(const float4*)&src[(size_t)gr * rstride + coloff + cq * 4];
            float xv[4] = {v.x, v.y, v.z, v.w};
            __nv_bfloat16 hh[4], ll[4];
#pragma unroll
            for (int i = 0; i < 4; i++) {
                hh[i] = __float2bfloat16(xv[i]);
                ll[i] = __float2bfloat16(xv[i] - __bfloat162float(hh[i]));
            }
            *(uint2*)(sAh + row * 144 + cq * 8) = *(const uint2*)hh;
            *(uint2*)(sAl + row * 144 + cq * 8) = *(const uint2*)ll;
        }
        {
            const __nv_bfloat16* bh =
                g_Whi + (size_t)(matBase + p) * 16384 + h * 64;
            const __nv_bfloat16* bl =
                g_Wlo + (size_t)(matBase + p) * 16384 + h * 64;
            for (int t = tid; t < 1024; t += 256) {
                int n = t >> 3, kb = t & 7;
                *(uint4*)(sBh + n * 144 + kb * 16) =
                    *(const uint4*)(bh + n * 128 + kb * 8);
                *(uint4*)(sBl + n * 144 + kb * 16) =
                    *(const uint4*)(bl + n * 128 + kb * 8);
            }
        }
        __syncthreads();

#pragma unroll
        for (int ks = 0; ks < 4; ks++) {
            uint32_t ah[2][4], al[2][4];
#pragma unroll
            for (int mt = 0; mt < 2; mt++) {
                uint32_t ao = (uint32_t)((wm0 + mt * 16 + la) * 144 +
                                         ks * 32 + lc);
                ldsm4(ah[mt], uAh + ao);
                ldsm4(al[mt], uAl + ao);
            }
#pragma unroll
            for (int nt = 0; nt < 8; nt++) {
                uint32_t bo = (uint32_t)((wn0 + nt * 8 + lb) * 144 +
                                         ks * 32 + lbm);
                uint32_t bh0, bh1, bl0, bl1;
                ldsm2(bh0, bh1, uBh + bo);
                ldsm2(bl0, bl1, uBl + bo);
#pragma unroll
                for (int mt = 0; mt < 2; mt++) {
                    mma16816(acc[mt][nt], ah[mt], bh0, bh1);
                    mma16816(acc[mt][nt], ah[mt], bl0, bl1);
                    mma16816(acc[mt][nt], al[mt], bh0, bh1);
                }
            }
        }
        __syncthreads();
    }

#pragma unroll
    for (int mt = 0; mt < 2; mt++) {
        int r0 = m0 + wm0 + mt * 16 + (lane >> 2);
#pragma unroll
        for (int nt = 0; nt < 8; nt++) {
            int cc = wn0 + nt * 8 + (lane & 3) * 2;
            float2 b2 = make_float2(sbias[cc], sbias[cc + 1]);
            if (r0 < M) {
                float2 o = make_float2(acc[mt][nt][0] + b2.x,
                                       acc[mt][nt][1] + b2.y);
                *(float2*)&C[(size_t)r0 * 128 + cc] = o;
            }
            if (r0 + 8 < M) {
                float2 o = make_float2(acc[mt][nt][2] + b2.x,
                                       acc[mt][nt][3] + b2.y);
                *(float2*)&C[(size_t)(r0 + 8) * 128 + cc] = o;
            }
        }
    }
}

// --------------------- HMMA embedding GEMM (K=1536 fused) ------------------
// cp.async pipeline: fp32 A stage (single) + double-buffered bf16 B.
// smem: bias 512 | stage 32768 | Ah 18432 | Al 18432 | B[2] 2x18432
#define ESN_ST   512
#define ESN_AH   33280
#define ESN_AL   51712
#define ESN_B    70144
#define ESN_TOTAL 107008

template <int NT0, int NT1>
__device__ __forceinline__ void emb_tiles_ld(uint32_t sAh, uint32_t sAl,
                                             uint32_t sBh, uint32_t sBl,
                                             int wid, int lane, float acc[8][4]) {
    int la = ((lane >> 3) & 1) * 8 + (lane & 7);
    int lc = (lane >> 4) * 16;
    int lb = lane & 7;
    int lbm = ((lane >> 3) & 1) * 16;
#pragma unroll
    for (int ks = 0; ks < 4; ks++) {
        uint32_t aoff = (uint32_t)((wid * 16 + la) * 144 + ks * 32 + lc);
        uint32_t ah[4], al[4];
        ldsm4(ah, sAh + aoff);
        ldsm4(al, sAl + aoff);
#pragma unroll
        for (int nt = NT0; nt < NT1; nt++) {
            uint32_t boff = (uint32_t)((nt * 8 + lb) * 144 + ks * 32 + lbm);
            uint32_t bh0, bh1, bl0, bl1;
            ldsm2(bh0, bh1, sBh + boff);
            ldsm2(bl0, bl1, sBl + boff);
            mma16816(acc[nt], ah, bh0, bh1);
            mma16816(acc[nt], ah, bl0, bl1);
            mma16816(acc[nt], al, bh0, bh1);
        }
    }
}

__global__ void __launch_bounds__(256, 2)
emb_hmma(const float* __restrict__ des, const float* __restrict__ tweet,
         const float* __restrict__ bd, const float* __restrict__ bt,
         float* __restrict__ C, int M) {
    extern __shared__ char sm[];
    uint32_t sb = (uint32_t)__cvta_generic_to_shared(sm);
    float* sbias = (float*)sm;

    int tid = threadIdx.x, lane = tid & 31, wid = tid >> 5;
    int m0 = blockIdx.x * 128;
    if (tid < 64) sbias[tid] = (tid < 28) ? bd[tid] : bt[tid - 28];

    auto issueA = [&](int kc) {
        const float* src = (kc < 12) ? des : tweet;
        int k0 = (kc < 12) ? kc * 64 : (kc - 12) * 64;
#pragma unroll
        for (int i = 0; i < 8; i++) {
            int t = tid + i * 256;
            int row = t >> 4, cq = t & 15;
            int gr = m0 + row;
            uint32_t dst = sb + ESN_ST + row * 256 + cq * 16;
            const float* s = src + (size_t)(gr < M ? gr : 0) * 768 + k0 + cq * 4;
            int szz = (gr < M) ? 16 : 0;
            asm volatile("cp.async.cg.shared.global [%0], [%1], 16, %2;"
                         :: "r"(dst), "l"(s), "r"(szz));
        }
    };
    auto issueB = [&](int kc) {
        int p = kc & 1;
        int ke = kc * 64;
#pragma unroll
        for (int i = 0; i < 4; i++) {
            int t = tid + i * 256;              // 0..1023
            int hl = t >> 9;                    // 0 hi, 1 lo
            int u = t & 511;
            int n = u >> 3, kb = u & 7;
            const __nv_bfloat16* s =
                (hl ? g_Elo : g_Ehi) + n * 1536 + ke + kb * 8;
            uint32_t dst = sb + ESN_B + (uint32_t)(p * 18432 + hl * 9216 +
                                                   n * 144 + kb * 16);
            asm volatile("cp.async.ca.shared.global [%0], [%1], 16;"
                         :: "r"(dst), "l"(s));
        }
    };

    issueA(0);
    issueB(0);
    asm volatile("cp.async.commit_group;" ::: "memory");

    float acc[8][4];
#pragma unroll
    for (int nt = 0; nt < 8; nt++)
#pragma unroll
        for (int q = 0; q < 4; q++) acc[nt][q] = 0.f;

    for (int kc = 0; kc < 24; kc++) {
        asm volatile("cp.async.wait_group 0;" ::: "memory");
        __syncthreads();
        // convert fp32 stage -> bf16 hi/lo A tiles
#pragma unroll
        for (int i = 0; i < 8; i++) {
            int t = tid + i * 256;
            int row = t >> 4, cq = t & 15;
            float4 v = *(const float4*)(sm + ESN_ST + row * 256 + cq * 16);
            float xv[4] = {v.x, v.y, v.z, v.w};
            __nv_bfloat16 h[4], l[4];
#pragma unroll
            for (int q = 0; q < 4; q++) {
                h[q] = __float2bfloat16(xv[q]);
                l[q] = __float2bfloat16(xv[q] - __bfloat162float(h[q]));
            }
            *(uint2*)(sm + ESN_AH + row * 144 + cq * 8) = *(const uint2*)h;
            *(uint2*)(sm + ESN_AL + row * 144 + cq * 8) = *(const uint2*)l;
        }
        __syncthreads();
        if (kc < 23) { issueA(kc + 1); issueB(kc + 1); }
        asm volatile("cp.async.commit_group;" ::: "memory");

        uint32_t bh = sb + ESN_B + (uint32_t)((kc & 1) * 18432);
        uint32_t bl = bh + 9216;
        if (kc < 12)
            emb_tiles_ld<0, 4>(sb + ESN_AH, sb + ESN_AL, bh, bl, wid, lane, acc);
        else
            emb_tiles_ld<3, 8>(sb + ESN_AH, sb + ESN_AL, bh, bl, wid, lane, acc);
        // next loop-top wait+sync orders compute reads vs next convert writes
    }

    // epilogue
#pragma unroll
    for (int nt = 0; nt < 8; nt++) {
        int c = nt * 8 + (lane & 3) * 2;
        float2 b2 = make_float2(sbias[c], sbias[c + 1]);
        int r0 = m0 + wid * 16 + (lane >> 2);
        if (r0 < M) {
            float2 o = make_float2(lrelu(acc[nt][0] + b2.x),
                                   lrelu(acc[nt][1] + b2.y));
            *(float2*)&C[(size_t)r0 * 128 + c] = o;
        }
        if (r0 + 8 < M) {
            float2 o = make_float2(lrelu(acc[nt][2] + b2.x),
                                   lrelu(acc[nt][3] + b2.y));
            *(float2*)&C[(size_t)(r0 + 8) * 128 + c] = o;
        }
    }
}

// ------------------------------- CSR build ---------------------------------
__global__ void k_zero(int n) {
    int i = blockIdx.x * blockDim.x + threadIdx.x;
    if (i < n) { g_c0[i] = 0; g_c1[i] = 0; }
}

__global__ void k_hist(const int* __restrict__ ei, const int* __restrict__ et,
                       int nE) {
    int i = blockIdx.x * blockDim.x + threadIdx.x;
    if (i >= nE) return;
    int d = ei[nE + i];
    if (et[i]) atomicAdd(&g_c1[d], 1);
    else       atomicAdd(&g_c0[d], 1);
}

__global__ void k_scan1(int n) {
    int tid = threadIdx.x;
    int i = blockIdx.x * 1024 + tid;
    int v = (i < n) ? (g_c0[i] + g_c1[i]) : 0;
    int x = v;
    int lane = tid & 31, w = tid >> 5;
#pragma unroll
    for (int d = 1; d < 32; d <<= 1) {
        int t = __shfl_up_sync(0xffffffffu, x, d);
        if (lane >= d) x += t;
    }
    __shared__ int wt[32];
    if (lane == 31) wt[w] = x;
    __syncthreads();
    if (w == 0) {
        int y = wt[lane];
#pragma unroll
        for (int d = 1; d < 32; d <<= 1) {
            int t = __shfl_up_sync(0xffffffffu, y, d);
            if (lane >= d) y += t;
        }
        wt[lane] = y;
    }
    __syncthreads();
    int off = (w > 0) ? wt[w - 1] : 0;
    int inc = x + off;
    if (i < n) g_rp[i] = inc - v;
    if (tid == 1023) g_bsum[blockIdx.x] = inc;
}

__global__ void k_scan2(int nb, int n, int nE) {
    int t = threadIdx.x;
    int lane = t & 31, w = t >> 5;
    int v = (t < nb) ? g_bsum[t] : 0;
    int x = v;
#pragma unroll
    for (int d = 1; d < 32; d <<= 1) {
        int s = __shfl_up_sync(0xffffffffu, x, d);
        if (lane >= d) x += s;
    }
    __shared__ int wt[4];
    if (lane == 31) wt[w] = x;
    __syncthreads();
    int off = 0;
    for (int k = 0; k < w; k++) off += wt[k];
    g_boff[t] = x + off - v;
    if (t == 0) g_rp[n] = nE;
}

__global__ void k_scan3(int n) {
    int i = blockIdx.x * blockDim.x + threadIdx.x;
    if (i >= n) return;
    int v = g_rp[i] + g_boff[i >> 10];
    g_rp[i] = v;
    g_cur[i] = v;
}

__global__ void k_fill(const int* __restrict__ ei, const int* __restrict__ et,
                       int nE) {
    int i = blockIdx.x * blockDim.x + threadIdx.x;
    if (i >= nE) return;
    int d = ei[nE + i];
    int pos = atomicAdd(&g_cur[d], 1);
    g_ep[pos] = (ei[i] << 1) | (et[i] ? 1 : 0);
}

// --------------------------- small embeddings ------------------------------
__global__ void k_small(const float* __restrict__ num,
                        const float* __restrict__ cat,
                        const float* __restrict__ nf,
                        const float* __restrict__ Wn, const float* __restrict__ bn,
                        const float* __restrict__ Wc, const float* __restrict__ bc,
                        const float* __restrict__ Ww, const float* __restrict__ bw,
                        float* __restrict__ xcat, int n) {
    int g = blockIdx.x * blockDim.x + threadIdx.x;
    if (g >= n * 64) return;
    int i = g >> 6, j = g & 63;
    float v;
    if (j < 12) {
        float s = bn[j];
#pragma unroll
        for (int k = 0; k < 7; k++)
            s = fmaf(num[(size_t)i * 7 + k], Wn[k * 12 + j], s);
        v = s;
    } else if (j < 52) {
        int c = j - 12;
        float s = bc[c];
#pragma unroll
        for (int k = 0; k < 11; k++)
            s = fmaf(cat[(size_t)i * 11 + k], Wc[k * 40 + c], s);
        v = s;
    } else {
        int c = j - 52;
        v = fmaf(nf[i], Ww[c], bw[c]);
    }
    xcat[(size_t)i * 128 + 64 + j] = lrelu(v);
}

// --------------------- pre-aggregation: z_r = mean_r(x_src) ----------------
__global__ void k_agg2(const float* __restrict__ x, float* __restrict__ z,
                       int n) {
    int g = blockIdx.x * blockDim.x + threadIdx.x;
    int gw = g >> 5;
    if (gw >= n) return;
    int lane = g & 31;
    int beg = g_rp[gw], end = g_rp[gw + 1];
    int c0 = g_c0[gw]; if (c0 < 1) c0 = 1;
    int c1 = g_c1[gw]; if (c1 < 1) c1 = 1;
    float w0 = 1.f / (float)c0;
    float w1 = 1.f / (float)c1;
    float4 a0 = make_float4(0.f, 0.f, 0.f, 0.f);
    float4 a1 = make_float4(0.f, 0.f, 0.f, 0.f);
    for (int e = beg; e < end; e++) {
        int p = g_ep[e];
        float4 v = ((const float4*)(x + (size_t)(p >> 1) * 128))[lane];
        if (p & 1) { a1.x += v.x; a1.y += v.y; a1.z += v.z; a1.w += v.w; }
        else       { a0.x += v.x; a0.y += v.y; a0.z += v.z; a0.w += v.w; }
    }
    a0.x *= w0; a0.y *= w0; a0.z *= w0; a0.w *= w0;
    a1.x *= w1; a1.y *= w1; a1.z *= w1; a1.w *= w1;
    ((float4*)(z + (size_t)gw * 256))[lane] = a0;
    ((float4*)(z + (size_t)gw * 256 + 128))[lane] = a1;
}

// ------------------------------ final linear -------------------------------
__global__ void k_final(const float* __restrict__ h, const float* __restrict__ W2,
                        const float* __restrict__ b2, float* __restrict__ out,
                        int n) {
    int g = blockIdx.x * blockDim.x + threadIdx.x;
    int gw = g >> 5;
    if (gw >= n) return;
    int lane = g & 31;
    const float* hr = h + (size_t)gw * 128;
    float a0 = 0.f, a1 = 0.f;
#pragma unroll
    for (int t = 0; t < 4; t++) {
        int k = lane + 32 * t;
        float hv = hr[k];
        float2 w = *(const float2*)&W2[k * 2];
        a0 = fmaf(hv, w.x, a0);
        a1 = fmaf(hv, w.y, a1);
    }
#pragma unroll
    for (int o = 16; o > 0; o >>= 1) {
        a0 += __shfl_xor_sync(0xffffffffu, a0, o);
        a1 += __shfl_xor_sync(0xffffffffu, a1, o);
    }
    if (lane == 0) {
        out[(size_t)gw * 2]     = a0 + b2[0];
        out[(size_t)gw * 2 + 1] = a1 + b2[1];
    }
}

// --------------------------------- launch ----------------------------------
extern "C" void kernel_launch(void* const* d_in, const int* in_sizes, int n_in,
                              void* d_out, int out_size) {
    const float* des    = (const float*)d_in[0];
    const float* tweet  = (const float*)d_in[1];
    const float* num    = (const float*)d_in[2];
    const float* cat    = (const float*)d_in[3];
    const float* nf     = (const float*)d_in[4];
    const int*   ei     = (const int*)  d_in[5];
    const int*   et     = (const int*)  d_in[6];
    const float* W_des  = (const float*)d_in[7];
    const float* b_des  = (const float*)d_in[8];
    const float* W_tw   = (const float*)d_in[9];
    const float* b_tw   = (const float*)d_in[10];
    const float* W_num  = (const float*)d_in[11];
    const float* b_num  = (const float*)d_in[12];
    const float* W_cat  = (const float*)d_in[13];
    const float* b_cat  = (const float*)d_in[14];
    const float* W_new  = (const float*)d_in[15];
    const float* b_new  = (const float*)d_in[16];
    const float* W_in   = (const float*)d_in[17];
    const float* b_in   = (const float*)d_in[18];
    const float* W_root = (const float*)d_in[19];
    const float* W_rel  = (const float*)d_in[20];
    const float* b_rg   = (const float*)d_in[21];
    const float* W_o1   = (const float*)d_in[22];
    const float* b_o1   = (const float*)d_in[23];
    const float* W_o2   = (const float*)d_in[24];
    const float* b_o2   = (const float*)d_in[25];

    int nN = in_sizes[0] / 768;
    int nE = in_sizes[6];
    if (nN > NMAX) nN = NMAX;
    if (nE > EMAX) nE = EMAX;

    float *bufA, *bufB, *bufZ;
    cudaGetSymbolAddress((void**)&bufA, g_bufA);
    cudaGetSymbolAddress((void**)&bufB, g_bufB);
    cudaGetSymbolAddress((void**)&bufZ, g_z);

    cudaFuncSetAttribute(mm_hmma<true>,
                         cudaFuncAttributeMaxDynamicSharedMemorySize, MMS_TOTAL);
    cudaFuncSetAttribute(mm_layer,
                         cudaFuncAttributeMaxDynamicSharedMemorySize, LS_TOTAL);
    cudaFuncSetAttribute(emb_hmma,
                         cudaFuncAttributeMaxDynamicSharedMemorySize, ESN_TOTAL);

    int gm     = (nN + 127) / 128;
    int gN256  = (nN + 255) / 256;
    int gE256  = (nE + 255) / 256;
    int gScan  = (nN + 1023) / 1024;
    int gWarpN = (nN * 32 + 255) / 256;

    // weight prep
    k_wprep<<<(14 * 16384 + 255) / 256, 256>>>(W_in, W_root, W_rel, W_o1);
    k_eprep<<<(64 * 1536 + 255) / 256, 256>>>(W_des, W_tw);

    // embeddings -> bufA
    k_small<<<(nN * 64 + 255) / 256, 256>>>(num, cat, nf, W_num, b_num,
                                            W_cat, b_cat, W_new, b_new,
                                            bufA, nN);
    emb_hmma<<<gm, 256, ESN_TOTAL>>>(des, tweet, b_des, b_tw, bufA, nN);

    // W_in (HMMA): bufA -> bufB, lrelu
    mm_hmma<true><<<dim3(gm, 1), 256, MMS_TOTAL>>>(bufA, 0, b_in, bufB, nN, 128);

    // CSR over dst
    k_zero<<<gN256, 256>>>(nN);
    k_hist<<<gE256, 256>>>(ei, et, nE);
    k_scan1<<<gScan, 1024>>>(nN);
    k_scan2<<<1, 128>>>(gScan, nN, nE);
    k_scan3<<<gN256, 256>>>(nN);
    k_fill<<<gE256, 256>>>(ei, et, nE);

    // 4 RGCN layers: aggregate x first, then fused K=384 GEMM
    float* x  = bufB;
    float* xn = bufA;
    for (int l = 0; l < 4; l++) {
        k_agg2<<<gWarpN, 256>>>(x, bufZ, nN);
        mm_layer<<<gm, 256, LS_TOTAL>>>(x, bufZ, 1 + 3 * l,
                                        b_rg + (size_t)l * 128, xn, nN);
        float* t = x; x = xn; xn = t;
    }
    // after 4 swaps: x == bufB

    // W_o1 (HMMA): x -> bufA, lrelu
    mm_hmma<true><<<dim3(gm, 1), 256, MMS_TOTAL>>>(x, 13, b_o1, bufA, nN, 128);

    // final [N,2]
    k_final<<<gWarpN, 256>>>(bufA, W_o2, b_o2, (float*)d_out, nN);
}

// round 14
// speedup vs baseline: 3.0750x; 1.0231x over previous
#include <cuda_runtime.h>
#include <cuda_bf16.h>
#include <cstdint>

// ---------------------------------------------------------------------------
// ESABotRGCN 4-layer pipeline.
//  - All GEMMs: mma.sync m16n8k16 bf16 (hi/lo split x3, fp32 acc), 2-deep
//    cp.async fp32 stage, fragments converted directly from stage (no smem
//    bf16 A tiles, no convert pass).
//  - emb_pipe: fused K=1536 embedding GEMM, B double-buffered cp.async.
//  - sq_pipe:  K=128 (W_in/W_o1) and K=384 (RGCN layer) GEMMs; B per-chunk
//    LDG->STS from L2. W_o1 variant fuses the final [128->2] head.
//  - RGCN layer: aggregate-first (mean commutes with linear map).
// ---------------------------------------------------------------------------
#define NMAX 100000
#define EMAX 600000

// ------------------------- scratch (device globals) ------------------------
__device__ float g_bufA[(size_t)NMAX * 128];
__device__ float g_bufB[(size_t)NMAX * 128];
__device__ float g_z   [(size_t)NMAX * 256];   // [z_rel0 | z_rel1]

__device__ __nv_bfloat16 g_Whi[14 * 128 * 128]; // [mat][n][k]  (W^T, split hi)
__device__ __nv_bfloat16 g_Wlo[14 * 128 * 128]; // [mat][n][k]  (W^T, split lo)
__device__ __nv_bfloat16 g_Ehi[64 * 1536];      // embedding W, block-diag
__device__ __nv_bfloat16 g_Elo[64 * 1536];

__device__ int g_c0[NMAX];
__device__ int g_c1[NMAX];
__device__ int g_rp[NMAX + 1];
__device__ int g_cur[NMAX];
__device__ int g_ep[EMAX];                     // (src<<1)|rel
__device__ int g_bsum[128];
__device__ int g_boff[128];

// ------------------------------ small helpers ------------------------------
__device__ __forceinline__ float lrelu(float v) { return fmaxf(v, 0.01f * v); }

__device__ __forceinline__ void mma16816(float* c, const uint32_t* a,
                                         uint32_t b0, uint32_t b1) {
    asm volatile(
        "mma.sync.aligned.m16n8k16.row.col.f32.bf16.bf16.f32 "
        "{%0,%1,%2,%3}, {%4,%5,%6,%7}, {%8,%9}, {%0,%1,%2,%3};"
        : "+f"(c[0]), "+f"(c[1]), "+f"(c[2]), "+f"(c[3])
        : "r"(a[0]), "r"(a[1]), "r"(a[2]), "r"(a[3]), "r"(b0), "r"(b1));
}

__device__ __forceinline__ void ldsm2(uint32_t& r0, uint32_t& r1, uint32_t a) {
    asm volatile("ldmatrix.sync.aligned.m8n8.x2.shared.b16 {%0,%1}, [%2];"
                 : "=r"(r0), "=r"(r1) : "r"(a));
}

// pack two fp32 -> bf16x2 {lo=first, hi=second}, round-to-nearest
__device__ __forceinline__ uint32_t bfpack(float lo, float hi) {
    uint32_t r;
    asm("cvt.rn.bf16x2.f32 %0, %1, %2;" : "=r"(r) : "f"(hi), "f"(lo));
    return r;
}

// Build hi/lo bf16 A fragments (m16k16) directly from fp32 stage (272B rows).
__device__ __forceinline__ void frag_cvt(uint32_t* ah, uint32_t* al,
                                         const char* stg, int row0, int ks,
                                         int lane) {
    const char* base = stg + (row0 + (lane >> 2)) * 272 +
                       (ks * 16 + 2 * (lane & 3)) * 4;
    float2 f[4];
    f[0] = *(const float2*)base;                 // rows 0-7 , k 0-7
    f[1] = *(const float2*)(base + 8 * 272);     // rows 8-15, k 0-7
    f[2] = *(const float2*)(base + 32);          // rows 0-7 , k 8-15
    f[3] = *(const float2*)(base + 8 * 272 + 32);// rows 8-15, k 8-15
#pragma unroll
    for (int i = 0; i < 4; i++) {
        uint32_t hp = bfpack(f[i].x, f[i].y);
        float h0 = __uint_as_float(hp << 16);
        float h1 = __uint_as_float(hp & 0xffff0000u);
        ah[i] = hp;
        al[i] = bfpack(f[i].x - h0, f[i].y - h1);
    }
}

// ------------------------------- weight prep -------------------------------
__global__ void k_wprep(const float* __restrict__ Win,
                        const float* __restrict__ Wroot,
                        const float* __restrict__ Wrel,
                        const float* __restrict__ Wo1) {
    int idx = blockIdx.x * blockDim.x + threadIdx.x;
    if (idx >= 14 * 16384) return;
    int m = idx >> 14;
    int r = idx & 16383;
    int n = r >> 7, k = r & 127;
    const float* src;
    if (m == 0) src = Win;
    else if (m == 13) src = Wo1;
    else {
        int l = (m - 1) / 3, j = (m - 1) % 3;
        src = (j == 0) ? (Wroot + (size_t)l * 16384)
                       : (Wrel + (size_t)(l * 2 + (j - 1)) * 16384);
    }
    float v = src[k * 128 + n];
    __nv_bfloat16 h = __float2bfloat16(v);
    g_Whi[idx] = h;
    g_Wlo[idx] = __float2bfloat16(v - __bfloat162float(h));
}

__global__ void k_eprep(const float* __restrict__ Wd,
                        const float* __restrict__ Wt) {
    int idx = blockIdx.x * blockDim.x + threadIdx.x;
    if (idx >= 64 * 1536) return;
    int n = idx / 1536, k = idx % 1536;
    float v = 0.f;
    if (n < 28 && k < 768) v = Wd[k * 28 + n];
    else if (n >= 28 && k >= 768) v = Wt[(k - 768) * 36 + (n - 28)];
    __nv_bfloat16 h = __float2bfloat16(v);
    g_Ehi[idx] = h;
    g_Elo[idx] = __float2bfloat16(v - __bfloat162float(h));
}

// --------------------- emb_pipe: K=1536 fused embeddings -------------------
// smem: hdr 512 | stage[2] 2x34816 | B[2] 2x(9216 hi + 9216 lo)
#define E_ST 512
#define E_B  70144
#define E_TOTAL 107008

template <int NT0, int NT1>
__device__ __forceinline__ void emb_mma(const char* stg, uint32_t ubh,
                                        uint32_t ubl, int wid, int lane,
                                        float acc[8][4]) {
    int lb = lane & 7;
    int lbm = ((lane >> 3) & 1) * 16;
#pragma unroll
    for (int ks = 0; ks < 4; ks++) {
        uint32_t ah[4], al[4];
        frag_cvt(ah, al, stg, wid * 16, ks, lane);
#pragma unroll
        for (int nt = NT0; nt < NT1; nt++) {
            uint32_t bo = (uint32_t)((nt * 8 + lb) * 144 + ks * 32 + lbm);
            uint32_t bh0, bh1, bl0, bl1;
            ldsm2(bh0, bh1, ubh + bo);
            ldsm2(bl0, bl1, ubl + bo);
            mma16816(acc[nt], ah, bh0, bh1);
            mma16816(acc[nt], ah, bl0, bl1);
            mma16816(acc[nt], al, bh0, bh1);
        }
    }
}

__global__ void __launch_bounds__(256, 2)
emb_pipe(const float* __restrict__ des, const float* __restrict__ tweet,
         const float* __restrict__ bd, const float* __restrict__ bt,
         float* __restrict__ C, int M) {
    extern __shared__ char sm[];
    uint32_t sb = (uint32_t)__cvta_generic_to_shared(sm);
    float* sbias = (float*)sm;
    int tid = threadIdx.x, lane = tid & 31, wid = tid >> 5;
    int m0 = blockIdx.x * 128;
    if (tid < 64) sbias[tid] = (tid < 28) ? bd[tid] : bt[tid - 28];

    auto issue = [&](int kc) {
        const float* src = (kc < 12) ? des : tweet;
        int k0 = (kc < 12) ? kc * 64 : (kc - 12) * 64;
        uint32_t sdst = sb + E_ST + (uint32_t)((kc & 1) * 34816);
#pragma unroll
        for (int i = 0; i < 8; i++) {
            int t = tid + i * 256;
            int row = t >> 4, cq = t & 15;
            int gr = m0 + row;
            uint32_t dst = sdst + (uint32_t)(row * 272 + cq * 16);
            const float* s = src + (size_t)(gr < M ? gr : 0) * 768 + k0 + cq * 4;
            int szz = (gr < M) ? 16 : 0;
            asm volatile("cp.async.cg.shared.global [%0], [%1], 16, %2;"
                         :: "r"(dst), "l"(s), "r"(szz));
        }
        int ke = kc * 64;
        uint32_t bdst = sb + E_B + (uint32_t)((kc & 1) * 18432);
#pragma unroll
        for (int i = 0; i < 4; i++) {
            int t = tid + i * 256;
            int hl = t >> 9;
            int u = t & 511;
            int n = u >> 3, kb = u & 7;
            const __nv_bfloat16* s = (hl ? g_Elo : g_Ehi) + n * 1536 + ke + kb * 8;
            uint32_t dst = bdst + (uint32_t)(hl * 9216 + n * 144 + kb * 16);
            asm volatile("cp.async.ca.shared.global [%0], [%1], 16;"
                         :: "r"(dst), "l"(s));
        }
    };

    issue(0); asm volatile("cp.async.commit_group;" ::: "memory");
    issue(1); asm volatile("cp.async.commit_group;" ::: "memory");

    float acc[8][4];
#pragma unroll
    for (int nt = 0; nt < 8; nt++)
#pragma unroll
        for (int q = 0; q < 4; q++) acc[nt][q] = 0.f;

    for (int kc = 0; kc < 24; kc++) {
        asm volatile("cp.async.wait_group 1;" ::: "memory");
        __syncthreads();
        const char* stg = sm + E_ST + (kc & 1) * 34816;
        uint32_t ubh = sb + E_B + (uint32_t)((kc & 1) * 18432);
        uint32_t ubl = ubh + 9216;
        if (kc < 12) emb_mma<0, 4>(stg, ubh, ubl, wid, lane, acc);
        else         emb_mma<3, 8>(stg, ubh, ubl, wid, lane, acc);
        __syncthreads();
        if (kc + 2 < 24) issue(kc + 2);
        asm volatile("cp.async.commit_group;" ::: "memory");
    }

#pragma unroll
    for (int nt = 0; nt < 8; nt++) {
        int c = nt * 8 + (lane & 3) * 2;
        float2 b2 = make_float2(sbias[c], sbias[c + 1]);
        int r0 = m0 + wid * 16 + (lane >> 2);
        if (r0 < M) {
            float2 o = make_float2(lrelu(acc[nt][0] + b2.x),
                                   lrelu(acc[nt][1] + b2.y));
            *(float2*)&C[(size_t)r0 * 128 + c] = o;
        }
        if (r0 + 8 < M) {
            float2 o = make_float2(lrelu(acc[nt][2] + b2.x),
                                   lrelu(acc[nt][3] + b2.y));
            *(float2*)&C[(size_t)(r0 + 8) * 128 + c] = o;
        }
    }
}

// ------------- sq_pipe: square (K=128) / layer (K=384) GEMMs ---------------
// MODE 0: out = act(x @ W[matBase] + bias)              (NC=2 chunks)
// MODE 1: out = x@W[mb] + z0@W[mb+1] + z1@W[mb+2] + b   (NC=6 chunks)
// FINAL : apply lrelu then project [128->2] with W2/b2 into C=[M,2].
// smem: hdr 2048 | stage[2] 2x34816 | Bh 18432 | Bl 18432
#define SQ_ST  2048
#define SQ_BH  71680
#define SQ_BL  90112
#define SQ_TOTAL 108544

template <int MODE, bool ACT, bool FINAL>
__global__ void __launch_bounds__(256, 2)
sq_pipe(const float* __restrict__ x, const float* __restrict__ z, int matBase,
        const float* __restrict__ bias, float* __restrict__ C,
        const float* __restrict__ W2, const float* __restrict__ b2, int M) {
    constexpr int NC = (MODE == 1) ? 6 : 2;
    extern __shared__ char sm[];
    uint32_t sb = (uint32_t)__cvta_generic_to_shared(sm);
    float* sbias = (float*)sm;                 // 128 floats
    float* sw2   = (float*)(sm + 512);         // 256 floats (FINAL)
    float* sb2   = (float*)(sm + 1536);        // 2 floats   (FINAL)
    int tid = threadIdx.x, lane = tid & 31, wid = tid >> 5;
    int m0 = blockIdx.x * 128;

    if (tid < 128) sbias[tid] = bias[tid];
    if (FINAL) {
        if (tid < 256) sw2[tid] = W2[tid];
        if (tid < 2) sb2[tid] = b2[tid];
    }

    auto issueA = [&](int c) {
        const float* src; int rs, co;
        if (MODE == 0) { src = x; rs = 128; co = c * 64; }
        else {
            int p = c >> 1, h = c & 1;
            if (p == 0) { src = x; rs = 128; co = h * 64; }
            else        { src = z; rs = 256; co = (p - 1) * 128 + h * 64; }
        }
        uint32_t sdst = sb + SQ_ST + (uint32_t)((c & 1) * 34816);
#pragma unroll
        for (int i = 0; i < 8; i++) {
            int t = tid + i * 256;
            int row = t >> 4, cq = t & 15;
            int gr = m0 + row;
            uint32_t dst = sdst + (uint32_t)(row * 272 + cq * 16);
            const float* s = src + (size_t)(gr < M ? gr : 0) * rs + co + cq * 4;
            int szz = (gr < M) ? 16 : 0;
            asm volatile("cp.async.cg.shared.global [%0], [%1], 16, %2;"
                         :: "r"(dst), "l"(s), "r"(szz));
        }
    };

    issueA(0); asm volatile("cp.async.commit_group;" ::: "memory");
    issueA(1); asm volatile("cp.async.commit_group;" ::: "memory");

    float acc[16][4];
#pragma unroll
    for (int nt = 0; nt < 16; nt++)
#pragma unroll
        for (int q = 0; q < 4; q++) acc[nt][q] = 0.f;

    int lb = lane & 7;
    int lbm = ((lane >> 3) & 1) * 16;

    for (int c = 0; c < NC; c++) {
        asm volatile("cp.async.wait_group 1;" ::: "memory");
        __syncthreads();
        // B(c): LDG from L2-resident prepped weights -> smem
        int p = (MODE == 1) ? (c >> 1) : 0;
        int h = (MODE == 1) ? (c & 1) : c;
        const __nv_bfloat16* bhp = g_Whi + (size_t)(matBase + p) * 16384 + h * 64;
        const __nv_bfloat16* blp = g_Wlo + (size_t)(matBase + p) * 16384 + h * 64;
        for (int t = tid; t < 1024; t += 256) {
            int n = t >> 3, kb = t & 7;
            *(uint4*)(sm + SQ_BH + n * 144 + kb * 16) =
                *(const uint4*)(bhp + n * 128 + kb * 8);
            *(uint4*)(sm + SQ_BL + n * 144 + kb * 16) =
                *(const uint4*)(blp + n * 128 + kb * 8);
        }
        __syncthreads();
        const char* stg = sm + SQ_ST + (c & 1) * 34816;
#pragma unroll
        for (int ks = 0; ks < 4; ks++) {
            uint32_t ah[4], al[4];
            frag_cvt(ah, al, stg, wid * 16, ks, lane);
#pragma unroll
            for (int nt = 0; nt < 16; nt++) {
                uint32_t bo = (uint32_t)((nt * 8 + lb) * 144 + ks * 32 + lbm);
                uint32_t bh0, bh1, bl0, bl1;
                ldsm2(bh0, bh1, sb + SQ_BH + bo);
                ldsm2(bl0, bl1, sb + SQ_BL + bo);
                mma16816(acc[nt], ah, bh0, bh1);
                mma16816(acc[nt], ah, bl0, bl1);
                mma16816(acc[nt], al, bh0, bh1);
            }
        }
        __syncthreads();
        if (c + 2 < NC) issueA(c + 2);
        asm volatile("cp.async.commit_group;" ::: "memory");
    }

    int r0 = m0 + wid * 16 + (lane >> 2);
    if (!FINAL) {
#pragma unroll
        for (int nt = 0; nt < 16; nt++) {
            int cc = nt * 8 + (lane & 3) * 2;
            float2 bb = make_float2(sbias[cc], sbias[cc + 1]);
            if (r0 < M) {
                float2 o = make_float2(acc[nt][0] + bb.x, acc[nt][1] + bb.y);
                if (ACT) { o.x = lrelu(o.x); o.y = lrelu(o.y); }
                *(float2*)&C[(size_t)r0 * 128 + cc] = o;
            }
            if (r0 + 8 < M) {
                float2 o = make_float2(acc[nt][2] + bb.x, acc[nt][3] + bb.y);
                if (ACT) { o.x = lrelu(o.x); o.y = lrelu(o.y); }
                *(float2*)&C[(size_t)(r0 + 8) * 128 + cc] = o;
            }
        }
    } else {
        float p0 = 0.f, p1 = 0.f, q0 = 0.f, q1 = 0.f;
#pragma unroll
        for (int nt = 0; nt < 16; nt++) {
            int cc = nt * 8 + (lane & 3) * 2;
            float b0 = sbias[cc], b1 = sbias[cc + 1];
            float v0 = lrelu(acc[nt][0] + b0), v1 = lrelu(acc[nt][1] + b1);
            float u0 = lrelu(acc[nt][2] + b0), u1 = lrelu(acc[nt][3] + b1);
            float w00 = sw2[cc * 2], w01 = sw2[cc * 2 + 1];
            float w10 = sw2[cc * 2 + 2], w11 = sw2[cc * 2 + 3];
            p0 += v0 * w00 + v1 * w10;  p1 += v0 * w01 + v1 * w11;
            q0 += u0 * w00 + u1 * w10;  q1 += u0 * w01 + u1 * w11;
        }
#pragma unroll
        for (int o = 1; o <= 2; o <<= 1) {
            p0 += __shfl_xor_sync(0xffffffffu, p0, o);
            p1 += __shfl_xor_sync(0xffffffffu, p1, o);
            q0 += __shfl_xor_sync(0xffffffffu, q0, o);
            q1 += __shfl_xor_sync(0xffffffffu, q1, o);
        }
        if ((lane & 3) == 0) {
            if (r0 < M) {
                C[(size_t)r0 * 2]     = p0 + sb2[0];
                C[(size_t)r0 * 2 + 1] = p1 + sb2[1];
            }
            if (r0 + 8 < M) {
                C[(size_t)(r0 + 8) * 2]     = q0 + sb2[0];
                C[(size_t)(r0 + 8) * 2 + 1] = q1 + sb2[1];
            }
        }
    }
}

// ------------------------------- CSR build ---------------------------------
__global__ void k_zero(int n) {
    int i = blockIdx.x * blockDim.x + threadIdx.x;
    if (i < n) { g_c0[i] = 0; g_c1[i] = 0; }
}

__global__ void k_hist(const int* __restrict__ ei, const int* __restrict__ et,
                       int nE) {
    int i = blockIdx.x * blockDim.x + threadIdx.x;
    if (i >= nE) return;
    int d = ei[nE + i];
    if (et[i]) atomicAdd(&g_c1[d], 1);
    else       atomicAdd(&g_c0[d], 1);
}

__global__ void k_scan1(int n) {
    int tid = threadIdx.x;
    int i = blockIdx.x * 1024 + tid;
    int v = (i < n) ? (g_c0[i] + g_c1[i]) : 0;
    int x = v;
    int lane = tid & 31, w = tid >> 5;
#pragma unroll
    for (int d = 1; d < 32; d <<= 1) {
        int t = __shfl_up_sync(0xffffffffu, x, d);
        if (lane >= d) x += t;
    }
    __shared__ int wt[32];
    if (lane == 31) wt[w] = x;
    __syncthreads();
    if (w == 0) {
        int y = wt[lane];
#pragma unroll
        for (int d = 1; d < 32; d <<= 1) {
            int t = __shfl_up_sync(0xffffffffu, y, d);
            if (lane >= d) y += t;
        }
        wt[lane] = y;
    }
    __syncthreads();
    int off = (w > 0) ? wt[w - 1] : 0;
    int inc = x + off;
    if (i < n) g_rp[i] = inc - v;
    if (tid == 1023) g_bsum[blockIdx.x] = inc;
}

__global__ void k_scan2(int nb, int n, int nE) {
    int t = threadIdx.x;
    int lane = t & 31, w = t >> 5;
    int v = (t < nb) ? g_bsum[t] : 0;
    int x = v;
#pragma unroll
    for (int d = 1; d < 32; d <<= 1) {
        int s = __shfl_up_sync(0xffffffffu, x, d);
        if (lane >= d) x += s;
    }
    __shared__ int wt[4];
    if (lane == 31) wt[w] = x;
    __syncthreads();
    int off = 0;
    for (int k = 0; k < w; k++) off += wt[k];
    g_boff[t] = x + off - v;
    if (t == 0) g_rp[n] = nE;
}

__global__ void k_scan3(int n) {
    int i = blockIdx.x * blockDim.x + threadIdx.x;
    if (i >= n) return;
    int v = g_rp[i] + g_boff[i >> 10];
    g_rp[i] = v;
    g_cur[i] = v;
}

__global__ void k_fill(const int* __restrict__ ei, const int* __restrict__ et,
                       int nE) {
    int i = blockIdx.x * blockDim.x + threadIdx.x;
    if (i >= nE) return;
    int d = ei[nE + i];
    int pos = atomicAdd(&g_cur[d], 1);
    g_ep[pos] = (ei[i] << 1) | (et[i] ? 1 : 0);
}

// --------------------------- small embeddings ------------------------------
__global__ void k_small(const float* __restrict__ num,
                        const float* __restrict__ cat,
                        const float* __restrict__ nf,
                        const float* __restrict__ Wn, const float* __restrict__ bn,
                        const float* __restrict__ Wc, const float* __restrict__ bc,
                        const float* __restrict__ Ww, const float* __restrict__ bw,
                        float* __restrict__ xcat, int n) {
    int g = blockIdx.x * blockDim.x + threadIdx.x;
    if (g >= n * 64) return;
    int i = g >> 6, j = g & 63;
    float v;
    if (j < 12) {
        float s = bn[j];
#pragma unroll
        for (int k = 0; k < 7; k++)
            s = fmaf(num[(size_t)i * 7 + k], Wn[k * 12 + j], s);
        v = s;
    } else if (j < 52) {
        int c = j - 12;
        float s = bc[c];
#pragma unroll
        for (int k = 0; k < 11; k++)
            s = fmaf(cat[(size_t)i * 11 + k], Wc[k * 40 + c], s);
        v = s;
    } else {
        int c = j - 52;
        v = fmaf(nf[i], Ww[c], bw[c]);
    }
    xcat[(size_t)i * 128 + 64 + j] = lrelu(v);
}

// --------------------- pre-aggregation: z_r = mean_r(x_src) ----------------
__global__ void k_agg2(const float* __restrict__ x, float* __restrict__ z,
                       int n) {
    int g = blockIdx.x * blockDim.x + threadIdx.x;
    int gw = g >> 5;
    if (gw >= n) return;
    int lane = g & 31;
    int beg = g_rp[gw], end = g_rp[gw + 1];
    int c0 = g_c0[gw]; if (c0 < 1) c0 = 1;
    int c1 = g_c1[gw]; if (c1 < 1) c1 = 1;
    float w0 = 1.f / (float)c0;
    float w1 = 1.f / (float)c1;
    float4 a0 = make_float4(0.f, 0.f, 0.f, 0.f);
    float4 a1 = make_float4(0.f, 0.f, 0.f, 0.f);
    for (int e = beg; e < end; e++) {
        int p = g_ep[e];
        float4 v = ((const float4*)(x + (size_t)(p >> 1) * 128))[lane];
        if (p & 1) { a1.x += v.x; a1.y += v.y; a1.z += v.z; a1.w += v.w; }
        else       { a0.x += v.x; a0.y += v.y; a0.z += v.z; a0.w += v.w; }
    }
    a0.x *= w0; a0.y *= w0; a0.z *= w0; a0.w *= w0;
    a1.x *= w1; a1.y *= w1; a1.z *= w1; a1.w *= w1;
    ((float4*)(z + (size_t)gw * 256))[lane] = a0;
    ((float4*)(z + (size_t)gw * 256 + 128))[lane] = a1;
}

// --------------------------------- launch ----------------------------------
extern "C" void kernel_launch(void* const* d_in, const int* in_sizes, int n_in,
                              void* d_out, int out_size) {
    const float* des    = (const float*)d_in[0];
    const float* tweet  = (const float*)d_in[1];
    const float* num    = (const float*)d_in[2];
    const float* cat    = (const float*)d_in[3];
    const float* nf     = (const float*)d_in[4];
    const int*   ei     = (const int*)  d_in[5];
    const int*   et     = (const int*)  d_in[6];
    const float* W_des  = (const float*)d_in[7];
    const float* b_des  = (const float*)d_in[8];
    const float* W_tw   = (const float*)d_in[9];
    const float* b_tw   = (const float*)d_in[10];
    const float* W_num  = (const float*)d_in[11];
    const float* b_num  = (const float*)d_in[12];
    const float* W_cat  = (const float*)d_in[13];
    const float* b_cat  = (const float*)d_in[14];
    const float* W_new  = (const float*)d_in[15];
    const float* b_new  = (const float*)d_in[16];
    const float* W_in   = (const float*)d_in[17];
    const float* b_in   = (const float*)d_in[18];
    const float* W_root = (const float*)d_in[19];
    const float* W_rel  = (const float*)d_in[20];
    const float* b_rg   = (const float*)d_in[21];
    const float* W_o1   = (const float*)d_in[22];
    const float* b_o1   = (const float*)d_in[23];
    const float* W_o2   = (const float*)d_in[24];
    const float* b_o2   = (const float*)d_in[25];

    int nN = in_sizes[0] / 768;
    int nE = in_sizes[6];
    if (nN > NMAX) nN = NMAX;
    if (nE > EMAX) nE = EMAX;

    float *bufA, *bufB, *bufZ;
    cudaGetSymbolAddress((void**)&bufA, g_bufA);
    cudaGetSymbolAddress((void**)&bufB, g_bufB);
    cudaGetSymbolAddress((void**)&bufZ, g_z);

    cudaFuncSetAttribute(emb_pipe,
                         cudaFuncAttributeMaxDynamicSharedMemorySize, E_TOTAL);
    cudaFuncSetAttribute(sq_pipe<0, true, false>,
                         cudaFuncAttributeMaxDynamicSharedMemorySize, SQ_TOTAL);
    cudaFuncSetAttribute(sq_pipe<1, false, false>,
                         cudaFuncAttributeMaxDynamicSharedMemorySize, SQ_TOTAL);
    cudaFuncSetAttribute(sq_pipe<0, true, true>,
                         cudaFuncAttributeMaxDynamicSharedMemorySize, SQ_TOTAL);

    int gm     = (nN + 127) / 128;
    int gN256  = (nN + 255) / 256;
    int gE256  = (nE + 255) / 256;
    int gScan  = (nN + 1023) / 1024;
    int gWarpN = (nN * 32 + 255) / 256;

    // weight prep
    k_wprep<<<(14 * 16384 + 255) / 256, 256>>>(W_in, W_root, W_rel, W_o1);
    k_eprep<<<(64 * 1536 + 255) / 256, 256>>>(W_des, W_tw);

    // embeddings -> bufA
    k_small<<<(nN * 64 + 255) / 256, 256>>>(num, cat, nf, W_num, b_num,
                                            W_cat, b_cat, W_new, b_new,
                                            bufA, nN);
    emb_pipe<<<gm, 256, E_TOTAL>>>(des, tweet, b_des, b_tw, bufA, nN);

    // W_in: bufA -> bufB, lrelu
    sq_pipe<0, true, false><<<gm, 256, SQ_TOTAL>>>(
        bufA, nullptr, 0, b_in, bufB, nullptr, nullptr, nN);

    // CSR over dst
    k_zero<<<gN256, 256>>>(nN);
    k_hist<<<gE256, 256>>>(ei, et, nE);
    k_scan1<<<gScan, 1024>>>(nN);
    k_scan2<<<1, 128>>>(gScan, nN, nE);
    k_scan3<<<gN256, 256>>>(nN);
    k_fill<<<gE256, 256>>>(ei, et, nE);

    // 4 RGCN layers: aggregate x first, then fused K=384 GEMM
    float* x  = bufB;
    float* xn = bufA;
    for (int l = 0; l < 4; l++) {
        k_agg2<<<gWarpN, 256>>>(x, bufZ, nN);
        sq_pipe<1, false, false><<<gm, 256, SQ_TOTAL>>>(
            x, bufZ, 1 + 3 * l, b_rg + (size_t)l * 128, xn,
            nullptr, nullptr, nN);
        float* t = x; x = xn; xn = t;
    }
    // after 4 swaps: x == bufB

    // W_o1 + final head fused: x -> d_out [N,2]
    sq_pipe<0, true, true><<<gm, 256, SQ_TOTAL>>>(
        x, nullptr, 13, b_o1, (float*)d_out, W_o2, b_o2, nN);
}

// round 15
// speedup vs baseline: 3.0863x; 1.0037x over previous
#include <cuda_runtime.h>
#include <cuda_bf16.h>
#include <cstdint>

// ---------------------------------------------------------------------------
// ESABotRGCN 4-layer pipeline.  64-row M-tiles, warp-split N.
//  - All GEMMs: mma.sync m16n8k16 bf16 (hi/lo split x3, fp32 acc), cp.async
//    fp32 stage, fragments converted from stage in registers.
//  - emb_pipe: K=1536 fused embedding GEMM, 3-deep A+B pipeline, 2 blk/SM.
//  - sq_pipe:  K=128 / K=384 GEMMs, 2-deep A stage, 3 blk/SM; W_o1 variant
//    fuses the final [128->2] head (cross-warp reduce via smem).
//  - RGCN layer: aggregate-first (mean commutes with linear map).
// ---------------------------------------------------------------------------
#define NMAX 100000
#define EMAX 600000

// ------------------------- scratch (device globals) ------------------------
__device__ float g_bufA[(size_t)NMAX * 128];
__device__ float g_bufB[(size_t)NMAX * 128];
__device__ float g_z   [(size_t)NMAX * 256];   // [z_rel0 | z_rel1]

__device__ __nv_bfloat16 g_Whi[14 * 128 * 128]; // [mat][n][k]  (W^T, split hi)
__device__ __nv_bfloat16 g_Wlo[14 * 128 * 128]; // [mat][n][k]  (W^T, split lo)
__device__ __nv_bfloat16 g_Ehi[64 * 1536];      // embedding W, block-diag
__device__ __nv_bfloat16 g_Elo[64 * 1536];

__device__ int g_c0[NMAX];
__device__ int g_c1[NMAX];
__device__ int g_rp[NMAX + 1];
__device__ int g_cur[NMAX];
__device__ int g_ep[EMAX];                     // (src<<1)|rel
__device__ int g_bsum[128];
__device__ int g_boff[128];

// ------------------------------ small helpers ------------------------------
__device__ __forceinline__ float lrelu(float v) { return fmaxf(v, 0.01f * v); }

__device__ __forceinline__ void mma16816(float* c, const uint32_t* a,
                                         uint32_t b0, uint32_t b1) {
    asm volatile(
        "mma.sync.aligned.m16n8k16.row.col.f32.bf16.bf16.f32 "
        "{%0,%1,%2,%3}, {%4,%5,%6,%7}, {%8,%9}, {%0,%1,%2,%3};"
        : "+f"(c[0]), "+f"(c[1]), "+f"(c[2]), "+f"(c[3])
        : "r"(a[0]), "r"(a[1]), "r"(a[2]), "r"(a[3]), "r"(b0), "r"(b1));
}

__device__ __forceinline__ void ldsm2(uint32_t& r0, uint32_t& r1, uint32_t a) {
    asm volatile("ldmatrix.sync.aligned.m8n8.x2.shared.b16 {%0,%1}, [%2];"
                 : "=r"(r0), "=r"(r1) : "r"(a));
}

// pack two fp32 -> bf16x2 {lo=first, hi=second}, round-to-nearest
__device__ __forceinline__ uint32_t bfpack(float lo, float hi) {
    uint32_t r;
    asm("cvt.rn.bf16x2.f32 %0, %1, %2;" : "=r"(r) : "f"(hi), "f"(lo));
    return r;
}

// Build hi/lo bf16 A fragments (m16k16) directly from fp32 stage (272B rows).
__device__ __forceinline__ void frag_cvt(uint32_t* ah, uint32_t* al,
                                         const char* stg, int row0, int ks,
                                         int lane) {
    const char* base = stg + (row0 + (lane >> 2)) * 272 +
                       (ks * 16 + 2 * (lane & 3)) * 4;
    float2 f[4];
    f[0] = *(const float2*)base;                 // rows 0-7 , k 0-7
    f[1] = *(const float2*)(base + 8 * 272);     // rows 8-15, k 0-7
    f[2] = *(const float2*)(base + 32);          // rows 0-7 , k 8-15
    f[3] = *(const float2*)(base + 8 * 272 + 32);// rows 8-15, k 8-15
#pragma unroll
    for (int i = 0; i < 4; i++) {
        uint32_t hp = bfpack(f[i].x, f[i].y);
        float h0 = __uint_as_float(hp << 16);
        float h1 = __uint_as_float(hp & 0xffff0000u);
        ah[i] = hp;
        al[i] = bfpack(f[i].x - h0, f[i].y - h1);
    }
}

// ------------------------------- weight prep -------------------------------
__global__ void k_wprep(const float* __restrict__ Win,
                        const float* __restrict__ Wroot,
                        const float* __restrict__ Wrel,
                        const float* __restrict__ Wo1) {
    int idx = blockIdx.x * blockDim.x + threadIdx.x;
    if (idx >= 14 * 16384) return;
    int m = idx >> 14;
    int r = idx & 16383;
    int n = r >> 7, k = r & 127;
    const float* src;
    if (m == 0) src = Win;
    else if (m == 13) src = Wo1;
    else {
        int l = (m - 1) / 3, j = (m - 1) % 3;
        src = (j == 0) ? (Wroot + (size_t)l * 16384)
                       : (Wrel + (size_t)(l * 2 + (j - 1)) * 16384);
    }
    float v = src[k * 128 + n];
    __nv_bfloat16 h = __float2bfloat16(v);
    g_Whi[idx] = h;
    g_Wlo[idx] = __float2bfloat16(v - __bfloat162float(h));
}

__global__ void k_eprep(const float* __restrict__ Wd,
                        const float* __restrict__ Wt) {
    int idx = blockIdx.x * blockDim.x + threadIdx.x;
    if (idx >= 64 * 1536) return;
    int n = idx / 1536, k = idx % 1536;
    float v = 0.f;
    if (n < 28 && k < 768) v = Wd[k * 28 + n];
    else if (n >= 28 && k >= 768) v = Wt[(k - 768) * 36 + (n - 28)];
    __nv_bfloat16 h = __float2bfloat16(v);
    g_Ehi[idx] = h;
    g_Elo[idx] = __float2bfloat16(v - __bfloat162float(h));
}

// --------------------- emb_pipe: K=1536 fused embeddings -------------------
// 64-row M-tile.  smem: hdr 512 | A stage[3] 3x17408 | B[3] 3x18432
#define E_ST 512
#define E_B  52736
#define E_TOTAL 108032

template <int NT0, int NT1>
__device__ __forceinline__ void emb_inner(const char* stg, uint32_t ubh,
                                          uint32_t ubl, int wid, int lane,
                                          float acc[4][4]) {
    int half = wid >> 2;
    int lb = lane & 7;
    int lbm = ((lane >> 3) & 1) * 16;
#pragma unroll
    for (int ks = 0; ks < 4; ks++) {
        uint32_t ah[4], al[4];
        frag_cvt(ah, al, stg, (wid & 3) * 16, ks, lane);
#pragma unroll
        for (int nt = NT0; nt < NT1; nt++) {
            uint32_t bo = (uint32_t)((half * 32 + nt * 8 + lb) * 144 +
                                     ks * 32 + lbm);
            uint32_t bh0, bh1, bl0, bl1;
            ldsm2(bh0, bh1, ubh + bo);
            ldsm2(bl0, bl1, ubl + bo);
            mma16816(acc[nt], ah, bh0, bh1);
            mma16816(acc[nt], ah, bl0, bl1);
            mma16816(acc[nt], al, bh0, bh1);
        }
    }
}

__global__ void __launch_bounds__(256, 2)
emb_pipe(const float* __restrict__ des, const float* __restrict__ tweet,
         const float* __restrict__ bd, const float* __restrict__ bt,
         float* __restrict__ C, int M) {
    extern __shared__ char sm[];
    uint32_t sb = (uint32_t)__cvta_generic_to_shared(sm);
    float* sbias = (float*)sm;
    int tid = threadIdx.x, lane = tid & 31, wid = tid >> 5;
    int m0 = blockIdx.x * 64;
    if (tid < 64) sbias[tid] = (tid < 28) ? bd[tid] : bt[tid - 28];

    auto issue = [&](int kc) {
        if (kc >= 24) return;
        int buf = kc % 3;
        const float* src = (kc < 12) ? des : tweet;
        int k0 = (kc < 12) ? kc * 64 : (kc - 12) * 64;
        uint32_t sdst = sb + E_ST + (uint32_t)(buf * 17408);
#pragma unroll
        for (int i = 0; i < 4; i++) {
            int t = tid + i * 256;
            int row = t >> 4, cq = t & 15;
            int gr = m0 + row;
            uint32_t dst = sdst + (uint32_t)(row * 272 + cq * 16);
            const float* s = src + (size_t)(gr < M ? gr : 0) * 768 + k0 + cq * 4;
            int szz = (gr < M) ? 16 : 0;
            asm volatile("cp.async.cg.shared.global [%0], [%1], 16, %2;"
                         :: "r"(dst), "l"(s), "r"(szz));
        }
        int ke = kc * 64;
        uint32_t bdst = sb + E_B + (uint32_t)(buf * 18432);
#pragma unroll
        for (int i = 0; i < 4; i++) {
            int t = tid + i * 256;
            int hl = t >> 9;
            int u = t & 511;
            int n = u >> 3, kb = u & 7;
            const __nv_bfloat16* s = (hl ? g_Elo : g_Ehi) + n * 1536 + ke + kb * 8;
            uint32_t dst = bdst + (uint32_t)(hl * 9216 + n * 144 + kb * 16);
            asm volatile("cp.async.ca.shared.global [%0], [%1], 16;"
                         :: "r"(dst), "l"(s));
        }
    };

    issue(0); asm volatile("cp.async.commit_group;" ::: "memory");
    issue(1); asm volatile("cp.async.commit_group;" ::: "memory");

    float acc[4][4];
#pragma unroll
    for (int nt = 0; nt < 4; nt++)
#pragma unroll
        for (int q = 0; q < 4; q++) acc[nt][q] = 0.f;

    int half = wid >> 2;
    for (int kc = 0; kc < 24; kc++) {
        asm volatile("cp.async.wait_group 1;" ::: "memory");
        __syncthreads();
        issue(kc + 2);
        asm volatile("cp.async.commit_group;" ::: "memory");
        const char* stg = sm + E_ST + (kc % 3) * 17408;
        uint32_t ubh = sb + E_B + (uint32_t)((kc % 3) * 18432);
        uint32_t ubl = ubh + 9216;
        if (kc < 12) {
            if (half == 0) emb_inner<0, 4>(stg, ubh, ubl, wid, lane, acc);
        } else {
            if (half == 0) emb_inner<3, 4>(stg, ubh, ubl, wid, lane, acc);
            else           emb_inner<0, 4>(stg, ubh, ubl, wid, lane, acc);
        }
        __syncthreads();
    }

#pragma unroll
    for (int nt = 0; nt < 4; nt++) {
        int c = half * 32 + nt * 8 + (lane & 3) * 2;
        float2 b2 = make_float2(sbias[c], sbias[c + 1]);
        int r0 = m0 + (wid & 3) * 16 + (lane >> 2);
        if (r0 < M) {
            float2 o = make_float2(lrelu(acc[nt][0] + b2.x),
                                   lrelu(acc[nt][1] + b2.y));
            *(float2*)&C[(size_t)r0 * 128 + c] = o;
        }
        if (r0 + 8 < M) {
            float2 o = make_float2(lrelu(acc[nt][2] + b2.x),
                                   lrelu(acc[nt][3] + b2.y));
            *(float2*)&C[(size_t)(r0 + 8) * 128 + c] = o;
        }
    }
}

// ------------- sq_pipe: square (K=128) / layer (K=384) GEMMs ---------------
// 64-row M-tile, warp n-halves.  3 blocks/SM.
// MODE 0: out = act(x @ W[matBase] + bias)              (NC=2 chunks)
// MODE 1: out = x@W[mb] + z0@W[mb+1] + z1@W[mb+2] + b   (NC=6 chunks)
// FINAL : lrelu then project [128->2] with W2/b2 into C=[M,2].
// smem: hdr 2048 | stage[2] 2x17408 | Bh 18432 | Bl 18432  = 73728
#define SQ_ST  2048
#define SQ_BH  36864
#define SQ_BL  55296
#define SQ_TOTAL 73728

template <int MODE, bool ACT, bool FINAL>
__global__ void __launch_bounds__(256, 3)
sq_pipe(const float* __restrict__ x, const float* __restrict__ z, int matBase,
        const float* __restrict__ bias, float* __restrict__ C,
        const float* __restrict__ W2, const float* __restrict__ b2, int M) {
    constexpr int NC = (MODE == 1) ? 6 : 2;
    extern __shared__ char sm[];
    uint32_t sb = (uint32_t)__cvta_generic_to_shared(sm);
    float* sbias = (float*)sm;                 // 128 floats
    float* sw2   = (float*)(sm + 512);         // 256 floats (FINAL)
    float* sb2   = (float*)(sm + 1536);        // 2 floats   (FINAL)
    int tid = threadIdx.x, lane = tid & 31, wid = tid >> 5;
    int half = wid >> 2;
    int m0 = blockIdx.x * 64;

    if (tid < 128) sbias[tid] = bias[tid];
    if (FINAL) {
        if (tid < 256) sw2[tid] = W2[tid];
        if (tid < 2) sb2[tid] = b2[tid];
    }

    auto issueA = [&](int c) {
        if (c >= NC) return;
        const float* src; int rs, co;
        if (MODE == 0) { src = x; rs = 128; co = c * 64; }
        else {
            int p = c >> 1, h = c & 1;
            if (p == 0) { src = x; rs = 128; co = h * 64; }
            else        { src = z; rs = 256; co = (p - 1) * 128 + h * 64; }
        }
        uint32_t sdst = sb + SQ_ST + (uint32_t)((c & 1) * 17408);
#pragma unroll
        for (int i = 0; i < 4; i++) {
            int t = tid + i * 256;
            int row = t >> 4, cq = t & 15;
            int gr = m0 + row;
            uint32_t dst = sdst + (uint32_t)(row * 272 + cq * 16);
            const float* s = src + (size_t)(gr < M ? gr : 0) * rs + co + cq * 4;
            int szz = (gr < M) ? 16 : 0;
            asm volatile("cp.async.cg.shared.global [%0], [%1], 16, %2;"
                         :: "r"(dst), "l"(s), "r"(szz));
        }
    };

    issueA(0); asm volatile("cp.async.commit_group;" ::: "memory");
    issueA(1); asm volatile("cp.async.commit_group;" ::: "memory");

    float acc[8][4];
#pragma unroll
    for (int nt = 0; nt < 8; nt++)
#pragma unroll
        for (int q = 0; q < 4; q++) acc[nt][q] = 0.f;

    int lb = lane & 7;
    int lbm = ((lane >> 3) & 1) * 16;

    for (int c = 0; c < NC; c++) {
        asm volatile("cp.async.wait_group 1;" ::: "memory");
        __syncthreads();
        // B(c): LDG from L2-resident prepped weights -> smem
        int p = (MODE == 1) ? (c >> 1) : 0;
        int h = (MODE == 1) ? (c & 1) : c;
        const __nv_bfloat16* bhp = g_Whi + (size_t)(matBase + p) * 16384 + h * 64;
        const __nv_bfloat16* blp = g_Wlo + (size_t)(matBase + p) * 16384 + h * 64;
#pragma unroll
        for (int i = 0; i < 8; i++) {
            int t = tid + i * 256;
            int hl = t >> 10;
            int u = t & 1023;
            int n = u >> 3, kb = u & 7;
            const __nv_bfloat16* s = (hl ? blp : bhp) + n * 128 + kb * 8;
            *(uint4*)(sm + (hl ? SQ_BL : SQ_BH) + n * 144 + kb * 16) =
                *(const uint4*)s;
        }
        __syncthreads();
        const char* stg = sm + SQ_ST + (c & 1) * 17408;
#pragma unroll
        for (int ks = 0; ks < 4; ks++) {
            uint32_t ah[4], al[4];
            frag_cvt(ah, al, stg, (wid & 3) * 16, ks, lane);
#pragma unroll
            for (int nt = 0; nt < 8; nt++) {
                uint32_t bo = (uint32_t)((half * 64 + nt * 8 + lb) * 144 +
                                         ks * 32 + lbm);
                uint32_t bh0, bh1, bl0, bl1;
                ldsm2(bh0, bh1, sb + SQ_BH + bo);
                ldsm2(bl0, bl1, sb + SQ_BL + bo);
                mma16816(acc[nt], ah, bh0, bh1);
                mma16816(acc[nt], ah, bl0, bl1);
                mma16816(acc[nt], al, bh0, bh1);
            }
        }
        __syncthreads();
        issueA(c + 2);
        asm volatile("cp.async.commit_group;" ::: "memory");
    }

    int r0 = m0 + (wid & 3) * 16 + (lane >> 2);
    if (!FINAL) {
#pragma unroll
        for (int nt = 0; nt < 8; nt++) {
            int cc = half * 64 + nt * 8 + (lane & 3) * 2;
            float2 bb = make_float2(sbias[cc], sbias[cc + 1]);
            if (r0 < M) {
                float2 o = make_float2(acc[nt][0] + bb.x, acc[nt][1] + bb.y);
                if (ACT) { o.x = lrelu(o.x); o.y = lrelu(o.y); }
                *(float2*)&C[(size_t)r0 * 128 + cc] = o;
            }
            if (r0 + 8 < M) {
                float2 o = make_float2(acc[nt][2] + bb.x, acc[nt][3] + bb.y);
                if (ACT) { o.x = lrelu(o.x); o.y = lrelu(o.y); }
                *(float2*)&C[(size_t)(r0 + 8) * 128 + cc] = o;
            }
        }
    } else {
        float p0 = 0.f, p1 = 0.f, q0 = 0.f, q1 = 0.f;
#pragma unroll
        for (int nt = 0; nt < 8; nt++) {
            int cc = half * 64 + nt * 8 + (lane & 3) * 2;
            float b0 = sbias[cc], b1 = sbias[cc + 1];
            float v0 = lrelu(acc[nt][0] + b0), v1 = lrelu(acc[nt][1] + b1);
            float u0 = lrelu(acc[nt][2] + b0), u1 = lrelu(acc[nt][3] + b1);
            float w00 = sw2[cc * 2], w01 = sw2[cc * 2 + 1];
            float w10 = sw2[cc * 2 + 2], w11 = sw2[cc * 2 + 3];
            p0 += v0 * w00 + v1 * w10;  p1 += v0 * w01 + v1 * w11;
            q0 += u0 * w00 + u1 * w10;  q1 += u0 * w01 + u1 * w11;
        }
#pragma unroll
        for (int o = 1; o <= 2; o <<= 1) {
            p0 += __shfl_xor_sync(0xffffffffu, p0, o);
            p1 += __shfl_xor_sync(0xffffffffu, p1, o);
            q0 += __shfl_xor_sync(0xffffffffu, q0, o);
            q1 += __shfl_xor_sync(0xffffffffu, q1, o);
        }
        // cross-warp combine (two n-halves share rows) via reused stage smem
        float* sred = (float*)(sm + SQ_ST);       // 2 halves x 64 rows x 2
        if ((lane & 3) == 0) {
            int rl = (wid & 3) * 16 + (lane >> 2);
            sred[half * 128 + rl * 2]           = p0;
            sred[half * 128 + rl * 2 + 1]       = p1;
            sred[half * 128 + (rl + 8) * 2]     = q0;
            sred[half * 128 + (rl + 8) * 2 + 1] = q1;
        }
        __syncthreads();
        if (tid < 128) {
            int row = tid >> 1, o = tid & 1;
            int gr = m0 + row;
            if (gr < M)
                C[(size_t)gr * 2 + o] =
                    sred[row * 2 + o] + sred[128 + row * 2 + o] + sb2[o];
        }
    }
}

// ------------------------------- CSR build ---------------------------------
__global__ void k_zero(int n) {
    int i = blockIdx.x * blockDim.x + threadIdx.x;
    if (i < n) { g_c0[i] = 0; g_c1[i] = 0; }
}

__global__ void k_hist(const int* __restrict__ ei, const int* __restrict__ et,
                       int nE) {
    int i = blockIdx.x * blockDim.x + threadIdx.x;
    if (i >= nE) return;
    int d = ei[nE + i];
    if (et[i]) atomicAdd(&g_c1[d], 1);
    else       atomicAdd(&g_c0[d], 1);
}

__global__ void k_scan1(int n) {
    int tid = threadIdx.x;
    int i = blockIdx.x * 1024 + tid;
    int v = (i < n) ? (g_c0[i] + g_c1[i]) : 0;
    int x = v;
    int lane = tid & 31, w = tid >> 5;
#pragma unroll
    for (int d = 1; d < 32; d <<= 1) {
        int t = __shfl_up_sync(0xffffffffu, x, d);
        if (lane >= d) x += t;
    }
    __shared__ int wt[32];
    if (lane == 31) wt[w] = x;
    __syncthreads();
    if (w == 0) {
        int y = wt[lane];
#pragma unroll
        for (int d = 1; d < 32; d <<= 1) {
            int t = __shfl_up_sync(0xffffffffu, y, d);
            if (lane >= d) y += t;
        }
        wt[lane] = y;
    }
    __syncthreads();
    int off = (w > 0) ? wt[w - 1] : 0;
    int inc = x + off;
    if (i < n) g_rp[i] = inc - v;
    if (tid == 1023) g_bsum[blockIdx.x] = inc;
}

__global__ void k_scan2(int nb, int n, int nE) {
    int t = threadIdx.x;
    int lane = t & 31, w = t >> 5;
    int v = (t < nb) ? g_bsum[t] : 0;
    int x = v;
#pragma unroll
    for (int d = 1; d < 32; d <<= 1) {
        int s = __shfl_up_sync(0xffffffffu, x, d);
        if (lane >= d) x += s;
    }
    __shared__ int wt[4];
    if (lane == 31) wt[w] = x;
    __syncthreads();
    int off = 0;
    for (int k = 0; k < w; k++) off += wt[k];
    g_boff[t] = x + off - v;
    if (t == 0) g_rp[n] = nE;
}

__global__ void k_scan3(int n) {
    int i = blockIdx.x * blockDim.x + threadIdx.x;
    if (i >= n) return;
    int v = g_rp[i] + g_boff[i >> 10];
    g_rp[i] = v;
    g_cur[i] = v;
}

__global__ void k_fill(const int* __restrict__ ei, const int* __restrict__ et,
                       int nE) {
    int i = blockIdx.x * blockDim.x + threadIdx.x;
    if (i >= nE) return;
    int d = ei[nE + i];
    int pos = atomicAdd(&g_cur[d], 1);
    g_ep[pos] = (ei[i] << 1) | (et[i] ? 1 : 0);
}

// --------------------------- small embeddings ------------------------------
__global__ void k_small(const float* __restrict__ num,
                        const float* __restrict__ cat,
                        const float* __restrict__ nf,
                        const float* __restrict__ Wn, const float* __restrict__ bn,
                        const float* __restrict__ Wc, const float* __restrict__ bc,
                        const float* __restrict__ Ww, const float* __restrict__ bw,
                        float* __restrict__ xcat, int n) {
    int g = blockIdx.x * blockDim.x + threadIdx.x;
    if (g >= n * 64) return;
    int i = g >> 6, j = g & 63;
    float v;
    if (j < 12) {
        float s = bn[j];
#pragma unroll
        for (int k = 0; k < 7; k++)
            s = fmaf(num[(size_t)i * 7 + k], Wn[k * 12 + j], s);
        v = s;
    } else if (j < 52) {
        int c = j - 12;
        float s = bc[c];
#pragma unroll
        for (int k = 0; k < 11; k++)
            s = fmaf(cat[(size_t)i * 11 + k], Wc[k * 40 + c], s);
        v = s;
    } else {
        int c = j - 52;
        v = fmaf(nf[i], Ww[c], bw[c]);
    }
    xcat[(size_t)i * 128 + 64 + j] = lrelu(v);
}

// --------------------- pre-aggregation: z_r = mean_r(x_src) ----------------
__global__ void k_agg2(const float* __restrict__ x, float* __restrict__ z,
                       int n) {
    int g = blockIdx.x * blockDim.x + threadIdx.x;
    int gw = g >> 5;
    if (gw >= n) return;
    int lane = g & 31;
    int beg = g_rp[gw], end = g_rp[gw + 1];
    int c0 = g_c0[gw]; if (c0 < 1) c0 = 1;
    int c1 = g_c1[gw]; if (c1 < 1) c1 = 1;
    float w0 = 1.f / (float)c0;
    float w1 = 1.f / (float)c1;
    float4 a0 = make_float4(0.f, 0.f, 0.f, 0.f);
    float4 a1 = make_float4(0.f, 0.f, 0.f, 0.f);
    for (int e = beg; e < end; e++) {
        int p = g_ep[e];
        float4 v = ((const float4*)(x + (size_t)(p >> 1) * 128))[lane];
        if (p & 1) { a1.x += v.x; a1.y += v.y; a1.z += v.z; a1.w += v.w; }
        else       { a0.x += v.x; a0.y += v.y; a0.z += v.z; a0.w += v.w; }
    }
    a0.x *= w0; a0.y *= w0; a0.z *= w0; a0.w *= w0;
    a1.x *= w1; a1.y *= w1; a1.z *= w1; a1.w *= w1;
    ((float4*)(z + (size_t)gw * 256))[lane] = a0;
    ((float4*)(z + (size_t)gw * 256 + 128))[lane] = a1;
}

// --------------------------------- launch ----------------------------------
extern "C" void kernel_launch(void* const* d_in, const int* in_sizes, int n_in,
                              void* d_out, int out_size) {
    const float* des    = (const float*)d_in[0];
    const float* tweet  = (const float*)d_in[1];
    const float* num    = (const float*)d_in[2];
    const float* cat    = (const float*)d_in[3];
    const float* nf     = (const float*)d_in[4];
    const int*   ei     = (const int*)  d_in[5];
    const int*   et     = (const int*)  d_in[6];
    const float* W_des  = (const float*)d_in[7];
    const float* b_des  = (const float*)d_in[8];
    const float* W_tw   = (const float*)d_in[9];
    const float* b_tw   = (const float*)d_in[10];
    const float* W_num  = (const float*)d_in[11];
    const float* b_num  = (const float*)d_in[12];
    const float* W_cat  = (const float*)d_in[13];
    const float* b_cat  = (const float*)d_in[14];
    const float* W_new  = (const float*)d_in[15];
    const float* b_new  = (const float*)d_in[16];
    const float* W_in   = (const float*)d_in[17];
    const float* b_in   = (const float*)d_in[18];
    const float* W_root = (const float*)d_in[19];
    const float* W_rel  = (const float*)d_in[20];
    const float* b_rg   = (const float*)d_in[21];
    const float* W_o1   = (const float*)d_in[22];
    const float* b_o1   = (const float*)d_in[23];
    const float* W_o2   = (const float*)d_in[24];
    const float* b_o2   = (const float*)d_in[25];

    int nN = in_sizes[0] / 768;
    int nE = in_sizes[6];
    if (nN > NMAX) nN = NMAX;
    if (nE > EMAX) nE = EMAX;

    float *bufA, *bufB, *bufZ;
    cudaGetSymbolAddress((void**)&bufA, g_bufA);
    cudaGetSymbolAddress((void**)&bufB, g_bufB);
    cudaGetSymbolAddress((void**)&bufZ, g_z);

    cudaFuncSetAttribute(emb_pipe,
                         cudaFuncAttributeMaxDynamicSharedMemorySize, E_TOTAL);
    cudaFuncSetAttribute(sq_pipe<0, true, false>,
                         cudaFuncAttributeMaxDynamicSharedMemorySize, SQ_TOTAL);
    cudaFuncSetAttribute(sq_pipe<1, false, false>,
                         cudaFuncAttributeMaxDynamicSharedMemorySize, SQ_TOTAL);
    cudaFuncSetAttribute(sq_pipe<0, true, true>,
                         cudaFuncAttributeMaxDynamicSharedMemorySize, SQ_TOTAL);

    int gm64   = (nN + 63) / 64;
    int gN256  = (nN + 255) / 256;
    int gE256  = (nE + 255) / 256;
    int gScan  = (nN + 1023) / 1024;
    int gWarpN = (nN * 32 + 255) / 256;

    // weight prep
    k_wprep<<<(14 * 16384 + 255) / 256, 256>>>(W_in, W_root, W_rel, W_o1);
    k_eprep<<<(64 * 1536 + 255) / 256, 256>>>(W_des, W_tw);

    // embeddings -> bufA
    k_small<<<(nN * 64 + 255) / 256, 256>>>(num, cat, nf, W_num, b_num,
                                            W_cat, b_cat, W_new, b_new,
                                            bufA, nN);
    emb_pipe<<<gm64, 256, E_TOTAL>>>(des, tweet, b_des, b_tw, bufA, nN);

    // W_in: bufA -> bufB, lrelu
    sq_pipe<0, true, false><<<gm64, 256, SQ_TOTAL>>>(
        bufA, nullptr, 0, b_in, bufB, nullptr, nullptr, nN);

    // CSR over dst
    k_zero<<<gN256, 256>>>(nN);
    k_hist<<<gE256, 256>>>(ei, et, nE);
    k_scan1<<<gScan, 1024>>>(nN);
    k_scan2<<<1, 128>>>(gScan, nN, nE);
    k_scan3<<<gN256, 256>>>(nN);
    k_fill<<<gE256, 256>>>(ei, et, nE);

    // 4 RGCN layers: aggregate x first, then fused K=384 GEMM
    float* x  = bufB;
    float* xn = bufA;
    for (int l = 0; l < 4; l++) {
        k_agg2<<<gWarpN, 256>>>(x, bufZ, nN);
        sq_pipe<1, false, false><<<gm64, 256, SQ_TOTAL>>>(
            x, bufZ, 1 + 3 * l, b_rg + (size_t)l * 128, xn,
            nullptr, nullptr, nN);
        float* t = x; x = xn; xn = t;
    }
    // after 4 swaps: x == bufB

    // W_o1 + final head fused: x -> d_out [N,2]
    sq_pipe<0, true, true><<<gm64, 256, SQ_TOTAL>>>(
        x, nullptr, 13, b_o1, (float*)d_out, W_o2, b_o2, nN);
}